// round 13
// baseline (speedup 1.0000x reference)
#include <cuda_runtime.h>
#include <cuda_bf16.h>
#include <math.h>
#include <cstdint>

#define NLAYERS 4
#define NHEADS  16
#define DMODEL  1024
#define DFF     4096
#define KW      7
#define SEQ     2048
#define CIN     4
#define COUT    4
#define HD      64
#define QKVS    3072
#define M1      (1 << 20)
#define WL_ELEMS (28 * M1)

// ---------------- scratch ----------------------------------------------------------
__device__ float g_x  [SEQ*DMODEL];
__device__ float g_qkv[SEQ*QKVS];
__device__ __nv_bfloat16 g_Ah [SEQ*DFF];
__device__ __nv_bfloat16 g_Al [SEQ*DFF];
__device__ __nv_bfloat16 g_Ah2[SEQ*DFF];
__device__ __nv_bfloat16 g_Al2[SEQ*DFF];
__device__ __nv_bfloat16 g_WBh[NLAYERS * WL_ELEMS];
__device__ __nv_bfloat16 g_WBl[NLAYERS * WL_ELEMS];
__device__ __nv_bfloat16 g_Qh[SEQ*DMODEL];
__device__ __nv_bfloat16 g_Ql[SEQ*DMODEL];
__device__ __nv_bfloat16 g_Kh[SEQ*DMODEL];
__device__ __nv_bfloat16 g_Kl[SEQ*DMODEL];
__device__ __nv_bfloat16 g_Vh[SEQ*DMODEL];
__device__ __nv_bfloat16 g_Vl[SEQ*DMODEL];

__device__ __forceinline__ uint32_t smem_u32(const void* p) {
    uint32_t a;
    asm("{ .reg .u64 t; cvta.to.shared.u64 t, %1; cvt.u32.u64 %0, t; }" : "=r"(a) : "l"(p));
    return a;
}

__device__ __forceinline__ void packhl(float x, float y, uint32_t& hi, uint32_t& lo) {
    __nv_bfloat16 hx = __float2bfloat16(x), hy = __float2bfloat16(y);
    __nv_bfloat16 lx = __float2bfloat16(x - __bfloat162float(hx));
    __nv_bfloat16 ly = __float2bfloat16(y - __bfloat162float(hy));
    hi = (uint32_t)__bfloat16_as_ushort(hx) | ((uint32_t)__bfloat16_as_ushort(hy) << 16);
    lo = (uint32_t)__bfloat16_as_ushort(lx) | ((uint32_t)__bfloat16_as_ushort(ly) << 16);
}

// ---------------- split ALL weights (round-11 coalesced layout) --------------------
__global__ void __launch_bounds__(256) splitall_kernel(
    const float* __restrict__ wq, const float* __restrict__ wk, const float* __restrict__ wv,
    const float* __restrict__ wo, const float* __restrict__ w1, const float* __restrict__ w2,
    const float* __restrict__ w3,
    __nv_bfloat16* __restrict__ dh, __nv_bfloat16* __restrict__ dl, int layer0)
{
    const int layer = layer0 + blockIdx.y;
    const size_t elem = ((size_t)blockIdx.x * 256 + threadIdx.x) * 8;
    const float* src;
    if (elem < 3 * (size_t)M1) {
        const float* t = (elem < (size_t)M1) ? wq : (elem < 2 * (size_t)M1) ? wk : wv;
        src = t + (size_t)layer * M1 + (elem & (M1 - 1));
    } else if (elem < 4 * (size_t)M1) {
        src = wo + (size_t)layer * M1 + (elem - 3 * (size_t)M1);
    } else if (elem < 8 * (size_t)M1) {
        src = w1 + (size_t)layer * 4 * M1 + (elem - 4 * (size_t)M1);
    } else if (elem < 24 * (size_t)M1) {
        src = w2 + (size_t)layer * 16 * M1 + (elem - 8 * (size_t)M1);
    } else {
        src = w3 + (size_t)layer * 4 * M1 + (elem - 24 * (size_t)M1);
    }
    __nv_bfloat16* oh = dh + (size_t)layer * WL_ELEMS + elem;
    __nv_bfloat16* ol = dl + (size_t)layer * WL_ELEMS + elem;
#pragma unroll
    for (int j = 0; j < 2; ++j) {
        float4 v = *(const float4*)(src + j * 4);
        uint2 ph, pl;
        packhl(v.x, v.y, ph.x, pl.x);
        packhl(v.z, v.w, ph.y, pl.y);
        *(uint2*)(oh + j * 4) = ph;
        *(uint2*)(ol + j * 4) = pl;
    }
}

// ================= bf16 HMMA GEMM: 128x128 CTA, 4 warps, 64x64 warp tiles ==========
#define GSTRIDE 80
#define AH_OFF 0
#define AL_OFF 10240
#define BH_OFF 20480
#define BL_OFF 30720
#define STAGE_SZ 40960
#define GSMEM_TOTAL (2 * STAGE_SZ)

__device__ __forceinline__ void ldm4(uint32_t addr, uint32_t& r0, uint32_t& r1,
                                     uint32_t& r2, uint32_t& r3) {
    asm volatile("ldmatrix.sync.aligned.m8n8.x4.shared.b16 {%0,%1,%2,%3}, [%4];"
                 : "=r"(r0), "=r"(r1), "=r"(r2), "=r"(r3) : "r"(addr));
}
__device__ __forceinline__ void ldm4t(uint32_t addr, uint32_t& r0, uint32_t& r1,
                                      uint32_t& r2, uint32_t& r3) {
    asm volatile("ldmatrix.sync.aligned.m8n8.x4.trans.shared.b16 {%0,%1,%2,%3}, [%4];"
                 : "=r"(r0), "=r"(r1), "=r"(r2), "=r"(r3) : "r"(addr));
}
__device__ __forceinline__ void mma16816(float* c, const uint32_t* a, const uint32_t* b) {
    asm volatile(
        "mma.sync.aligned.m16n8k16.row.col.f32.bf16.bf16.f32 "
        "{%0,%1,%2,%3}, {%4,%5,%6,%7}, {%8,%9}, {%0,%1,%2,%3};"
        : "+f"(c[0]), "+f"(c[1]), "+f"(c[2]), "+f"(c[3])
        : "r"(a[0]), "r"(a[1]), "r"(a[2]), "r"(a[3]), "r"(b[0]), "r"(b[1]));
}
__device__ __forceinline__ void cp16(uint32_t saddr, const void* gaddr) {
    asm volatile("cp.async.cg.shared.global [%0], [%1], 16;" :: "r"(saddr), "l"(gaddr));
}
#define CP_COMMIT() asm volatile("cp.async.commit_group;" ::: "memory")
#define CP_WAIT0()  asm volatile("cp.async.wait_group 0;" ::: "memory")

template<bool BIAS, bool RELU, bool RES, bool OSPLIT>
__global__ void __launch_bounds__(128, 2)
gemm_bf16(int K, int N,
          const __nv_bfloat16* __restrict__ Ah, const __nv_bfloat16* __restrict__ Al,
          const __nv_bfloat16* __restrict__ Bh, const __nv_bfloat16* __restrict__ Bl,
          const float* __restrict__ bias, const float* __restrict__ res,
          float* __restrict__ C,
          __nv_bfloat16* __restrict__ Chi, __nv_bfloat16* __restrict__ Clo)
{
    extern __shared__ __align__(128) char smem[];
    const uint32_t sb = smem_u32(smem);
    const int tid  = threadIdx.x;
    const int wid  = tid >> 5;
    const int lane = tid & 31;
    const int wm   = wid >> 1;        // 0..1 : 64 rows
    const int wn   = wid & 1;         // 0..1 : 64 cols
    const int m0   = blockIdx.y * 128;
    const int n0   = blockIdx.x * 128;

    float acc[4][8][4];
#pragma unroll
    for (int i = 0; i < 4; ++i)
#pragma unroll
        for (int j = 0; j < 8; ++j)
#pragma unroll
            for (int q = 0; q < 4; ++q) acc[i][j][q] = 0.0f;

    const int NC = K >> 5;

    // loader: 128 threads, each owns one 64B row in all 4 tiles
    const int sub = lane >> 3, r8 = lane & 7;
    const uint32_t a_lane_off = (uint32_t)(((sub & 1) * 8 + r8) * GSTRIDE + ((sub >> 1) * 8) * 2);
    const uint32_t b_lane_off = (uint32_t)((((sub >> 1) * 8) + r8) * GSTRIDE + ((sub & 1) * 8) * 2);

    auto issue = [&](int c) {
        const uint32_t stg  = sb + (uint32_t)(c & 1) * STAGE_SZ;
        const uint32_t soff = (uint32_t)(tid * GSTRIDE);
        const size_t   goff = (size_t)tid * K + (size_t)c * 32;
        const char* ah = (const char*)(Ah + (size_t)m0 * K + goff);
        const char* al = (const char*)(Al + (size_t)m0 * K + goff);
        const char* bh = (const char*)(Bh + (size_t)n0 * K + goff);
        const char* bl = (const char*)(Bl + (size_t)n0 * K + goff);
#pragma unroll
        for (int q = 0; q < 4; ++q) {
            cp16(stg + AH_OFF + soff + q * 16, ah + q * 16);
            cp16(stg + AL_OFF + soff + q * 16, al + q * 16);
            cp16(stg + BH_OFF + soff + q * 16, bh + q * 16);
            cp16(stg + BL_OFF + soff + q * 16, bl + q * 16);
        }
    };

    issue(0); CP_COMMIT();

    for (int c = 0; c < NC; ++c) {
        CP_WAIT0();
        __syncthreads();
        if (c + 1 < NC) { issue(c + 1); CP_COMMIT(); }

        const uint32_t stg  = sb + (uint32_t)(c & 1) * STAGE_SZ;
        const uint32_t ah_b = stg + AH_OFF + (uint32_t)(wm * 64) * GSTRIDE + a_lane_off;
        const uint32_t al_b = stg + AL_OFF + (uint32_t)(wm * 64) * GSTRIDE + a_lane_off;
        const uint32_t bh_b = stg + BH_OFF + (uint32_t)(wn * 64) * GSTRIDE + b_lane_off;
        const uint32_t bl_b = stg + BL_OFF + (uint32_t)(wn * 64) * GSTRIDE + b_lane_off;

#pragma unroll
        for (int ks = 0; ks < 2; ++ks) {
            const uint32_t ko = (uint32_t)(ks * 32);
            uint32_t ahh[4][4], bhh[8][2];
#pragma unroll
            for (int mt = 0; mt < 4; ++mt)
                ldm4(ah_b + (uint32_t)(mt * 16) * GSTRIDE + ko,
                     ahh[mt][0], ahh[mt][1], ahh[mt][2], ahh[mt][3]);
#pragma unroll
            for (int np = 0; np < 4; ++np)
                ldm4(bh_b + (uint32_t)(np * 16) * GSTRIDE + ko,
                     bhh[np*2][0], bhh[np*2][1], bhh[np*2+1][0], bhh[np*2+1][1]);
            // hi * hi
#pragma unroll
            for (int mt = 0; mt < 4; ++mt)
#pragma unroll
                for (int nt = 0; nt < 8; ++nt)
                    mma16816(acc[mt][nt], ahh[mt], bhh[nt]);
            // hi * lo (B lo)
            {
                uint32_t bhl[8][2];
#pragma unroll
                for (int np = 0; np < 4; ++np)
                    ldm4(bl_b + (uint32_t)(np * 16) * GSTRIDE + ko,
                         bhl[np*2][0], bhl[np*2][1], bhl[np*2+1][0], bhl[np*2+1][1]);
#pragma unroll
                for (int mt = 0; mt < 4; ++mt)
#pragma unroll
                    for (int nt = 0; nt < 8; ++nt)
                        mma16816(acc[mt][nt], ahh[mt], bhl[nt]);
            }
            // lo * hi (A lo)
            {
                uint32_t ahl[4][4];
#pragma unroll
                for (int mt = 0; mt < 4; ++mt)
                    ldm4(al_b + (uint32_t)(mt * 16) * GSTRIDE + ko,
                         ahl[mt][0], ahl[mt][1], ahl[mt][2], ahl[mt][3]);
#pragma unroll
                for (int mt = 0; mt < 4; ++mt)
#pragma unroll
                    for (int nt = 0; nt < 8; ++nt)
                        mma16816(acc[mt][nt], ahl[mt], bhh[nt]);
            }
        }
        __syncthreads();
    }

    // ---- epilogue ----
    const int erow = m0 + wm * 64 + (lane >> 2);
    const int ecol = n0 + wn * 64 + (lane & 3) * 2;
#pragma unroll
    for (int mt = 0; mt < 4; ++mt) {
#pragma unroll
        for (int nt = 0; nt < 8; ++nt) {
            const int r0 = erow + mt * 16;
            const int cc = ecol + nt * 8;
            float2 v0 = make_float2(acc[mt][nt][0], acc[mt][nt][1]);
            float2 v1 = make_float2(acc[mt][nt][2], acc[mt][nt][3]);
            if (BIAS) {
                float2 bb = *(const float2*)(bias + cc);
                v0.x += bb.x; v0.y += bb.y; v1.x += bb.x; v1.y += bb.y;
            }
            if (RELU) {
                v0.x = fmaxf(v0.x, 0.f); v0.y = fmaxf(v0.y, 0.f);
                v1.x = fmaxf(v1.x, 0.f); v1.y = fmaxf(v1.y, 0.f);
            }
            if (RES) {
                float2 r4 = *(const float2*)(res + (size_t)r0 * N + cc);
                v0.x += r4.x; v0.y += r4.y;
                float2 r5 = *(const float2*)(res + (size_t)(r0 + 8) * N + cc);
                v1.x += r5.x; v1.y += r5.y;
            }
            if (OSPLIT) {
                uint32_t h0, l0, h1, l1;
                packhl(v0.x, v0.y, h0, l0);
                packhl(v1.x, v1.y, h1, l1);
                *(uint32_t*)(Chi + (size_t)r0 * N + cc) = h0;
                *(uint32_t*)(Clo + (size_t)r0 * N + cc) = l0;
                *(uint32_t*)(Chi + (size_t)(r0 + 8) * N + cc) = h1;
                *(uint32_t*)(Clo + (size_t)(r0 + 8) * N + cc) = l1;
            } else {
                *(float2*)(C + (size_t)r0 * N + cc) = v0;
                *(float2*)(C + (size_t)(r0 + 8) * N + cc) = v1;
            }
        }
    }
}

// ---------------- conv_in ----------------------------------------------------------
__global__ void conv_in_kernel(const float* __restrict__ x,
                               const float* __restrict__ w,
                               const float* __restrict__ b,
                               float* __restrict__ h)
{
    int idx = blockIdx.x * blockDim.x + threadIdx.x;
    if (idx >= SEQ * DMODEL) return;
    int d = idx & (DMODEL - 1);
    int l = idx >> 10;
    float acc = b[d];
#pragma unroll
    for (int c = 0; c < CIN; ++c) {
#pragma unroll
        for (int t = 0; t < KW; ++t) {
            int lt = l + t - (KW - 1);
            if (lt >= 0) acc += w[(d * CIN + c) * KW + t] * x[c * SEQ + lt];
        }
    }
    h[idx] = fmaxf(acc, 0.0f);
}

// ---------------- conv_out ---------------------------------------------------------
__global__ void conv_out_kernel(const float* __restrict__ xb,
                                const float* __restrict__ w,
                                const float* __restrict__ b,
                                float* __restrict__ out)
{
    int l  = blockIdx.x;
    int co = blockIdx.y;
    float acc = 0.0f;
    for (int d = threadIdx.x; d < DMODEL; d += 128) {
        const float* wp = w + (size_t)(co * DMODEL + d) * KW;
#pragma unroll
        for (int t = 0; t < KW; ++t) {
            int lt = l + t - (KW - 1);
            if (lt >= 0) acc += wp[t] * xb[(size_t)lt * DMODEL + d];
        }
    }
#pragma unroll
    for (int s = 16; s >= 1; s >>= 1) acc += __shfl_xor_sync(0xffffffffu, acc, s);
    __shared__ float red[4];
    if ((threadIdx.x & 31) == 0) red[threadIdx.x >> 5] = acc;
    __syncthreads();
    if (threadIdx.x == 0)
        out[co * SEQ + l] = red[0] + red[1] + red[2] + red[3] + b[co];
}

// ---------------- RMSNorm -> hi/lo split -------------------------------------------
__global__ void __launch_bounds__(256) rmsnorm_split_kernel(const float* __restrict__ x,
                                                            const float* __restrict__ w,
                                                            const float* __restrict__ b,
                                                            __nv_bfloat16* __restrict__ hi,
                                                            __nv_bfloat16* __restrict__ lo)
{
    int l = blockIdx.x;
    const float* xr = x + (size_t)l * DMODEL;
    const int tid = threadIdx.x;
    float4 v = *(const float4*)(xr + tid * 4);
    float ss = v.x * v.x + v.y * v.y + v.z * v.z + v.w * v.w;
#pragma unroll
    for (int s = 16; s >= 1; s >>= 1) ss += __shfl_xor_sync(0xffffffffu, ss, s);
    __shared__ float red[8];
    __shared__ float sinv;
    if ((tid & 31) == 0) red[tid >> 5] = ss;
    __syncthreads();
    if (tid == 0) {
        float t = 0.0f;
#pragma unroll
        for (int i = 0; i < 8; ++i) t += red[i];
        sinv = rsqrtf(t * (1.0f / DMODEL) + 1e-5f);
    }
    __syncthreads();
    float inv = sinv;
    float4 wv = *(const float4*)(w + tid * 4);
    float4 bv = *(const float4*)(b + tid * 4);
    float y0 = v.x * inv * wv.x + bv.x;
    float y1 = v.y * inv * wv.y + bv.y;
    float y2 = v.z * inv * wv.z + bv.z;
    float y3 = v.w * inv * wv.w + bv.w;
    uint2 ph, pl;
    packhl(y0, y1, ph.x, pl.x);
    packhl(y2, y3, ph.y, pl.y);
    *(uint2*)(hi + (size_t)l * DMODEL + tid * 4) = ph;
    *(uint2*)(lo + (size_t)l * DMODEL + tid * 4) = pl;
}

// ---------------- RoPE + split -----------------------------------------------------
__device__ __forceinline__ void split1(float x, __nv_bfloat16* hi, __nv_bfloat16* lo, size_t o) {
    __nv_bfloat16 h = __float2bfloat16(x);
    hi[o] = h;
    lo[o] = __float2bfloat16(x - __bfloat162float(h));
}

__global__ void rope_split_kernel(const float* __restrict__ qkv,
                                  __nv_bfloat16* __restrict__ Qh, __nv_bfloat16* __restrict__ Ql,
                                  __nv_bfloat16* __restrict__ Kh, __nv_bfloat16* __restrict__ Kl,
                                  __nv_bfloat16* __restrict__ Vh, __nv_bfloat16* __restrict__ Vl)
{
    int idx = blockIdx.x * blockDim.x + threadIdx.x;
    if (idx >= SEQ * NHEADS * (HD / 2)) return;
    int j = idx & 31;
    int h = (idx >> 5) & (NHEADS - 1);
    int l = idx >> 9;
    float inv_freq = exp2f(-(float)j * (13.287712379549449f / 32.0f));
    float ang = (float)l * inv_freq;
    float s, c;
    sincosf(ang, &s, &c);
    size_t ib = (size_t)l * QKVS + h * HD + j;
    size_t ob = (size_t)l * DMODEL + h * HD + j;
    float q1 = qkv[ib], q2 = qkv[ib + 32];
    split1((q1 * c - q2 * s) * 0.125f, Qh, Ql, ob);
    split1((q2 * c + q1 * s) * 0.125f, Qh, Ql, ob + 32);
    float k1 = qkv[ib + DMODEL], k2 = qkv[ib + DMODEL + 32];
    split1(k1 * c - k2 * s, Kh, Kl, ob);
    split1(k2 * c + k1 * s, Kh, Kl, ob + 32);
    split1(qkv[ib + 2 * DMODEL], Vh, Vl, ob);
    split1(qkv[ib + 2 * DMODEL + 32], Vh, Vl, ob + 32);
}

// ---------------- MMA flash attention (bf16 3-term, fp32 softmax) ------------------
#define ASTRIDE 144
#define AMM_SMEM (6 * 64 * ASTRIDE)

__global__ void __launch_bounds__(128) attn_mma_kernel(
    const __nv_bfloat16* __restrict__ Qh, const __nv_bfloat16* __restrict__ Ql,
    const __nv_bfloat16* __restrict__ Kh, const __nv_bfloat16* __restrict__ Kl,
    const __nv_bfloat16* __restrict__ Vh, const __nv_bfloat16* __restrict__ Vl,
    __nv_bfloat16* __restrict__ Ohi, __nv_bfloat16* __restrict__ Olo)
{
    extern __shared__ __align__(128) char smem[];
    const uint32_t sb = smem_u32(smem);
    const int h  = blockIdx.y;
    const int qt = blockIdx.x;
    const int q0 = qt * 64;
    const int tid = threadIdx.x, wid = tid >> 5, lane = tid & 31;

    const uint32_t QHo = 0, QLo = 9216, KHo = 18432, KLo = 27648, VHo = 36864, VLo = 46080;

    {
        const int row = tid >> 1, ho = (tid & 1) * 64;
        const uint32_t so = (uint32_t)(row * ASTRIDE + ho);
        const char* gh = (const char*)(Qh + (size_t)(q0 + row) * DMODEL + h * HD) + ho;
        const char* gl = (const char*)(Ql + (size_t)(q0 + row) * DMODEL + h * HD) + ho;
#pragma unroll
        for (int i = 0; i < 4; ++i) {
            cp16(sb + QHo + so + i * 16, gh + i * 16);
            cp16(sb + QLo + so + i * 16, gl + i * 16);
        }
    }
    CP_COMMIT();
    CP_WAIT0();
    __syncthreads();

    const int sub = lane >> 3, r8v = lane & 7;
    const uint32_t a_off = (uint32_t)(((sub & 1) * 8 + r8v) * ASTRIDE + ((sub >> 1) * 8) * 2);
    const uint32_t b_off = (uint32_t)((((sub >> 1) * 8) + r8v) * ASTRIDE + (sub & 1) * 16);
    const uint32_t v_off = (uint32_t)(((sub & 1) * 8 + r8v) * ASTRIDE + (sub >> 1) * 16);

    uint32_t qfh[4][4], qfl[4][4];
#pragma unroll
    for (int ks = 0; ks < 4; ++ks) {
        ldm4(sb + QHo + (uint32_t)(wid * 16) * ASTRIDE + a_off + (uint32_t)(ks * 32),
             qfh[ks][0], qfh[ks][1], qfh[ks][2], qfh[ks][3]);
        ldm4(sb + QLo + (uint32_t)(wid * 16) * ASTRIDE + a_off + (uint32_t)(ks * 32),
             qfl[ks][0], qfl[ks][1], qfl[ks][2], qfl[ks][3]);
    }

    float m0 = -INFINITY, m1 = -INFINITY, l0 = 0.f, l1 = 0.f;
    float oa[8][4];
#pragma unroll
    for (int nt = 0; nt < 8; ++nt)
#pragma unroll
        for (int q = 0; q < 4; ++q) oa[nt][q] = 0.f;

    const int qi0 = q0 + wid * 16 + (lane >> 2);
    const int qi1 = qi0 + 8;

    for (int jt = 0; jt <= qt; ++jt) {
        __syncthreads();
        {
            const int row = tid >> 1, ho = (tid & 1) * 64;
            const uint32_t so = (uint32_t)(row * ASTRIDE + ho);
            const size_t g = (size_t)(jt * 64 + row) * DMODEL + h * HD;
            const char* pkh = (const char*)(Kh + g) + ho;
            const char* pkl = (const char*)(Kl + g) + ho;
            const char* pvh = (const char*)(Vh + g) + ho;
            const char* pvl = (const char*)(Vl + g) + ho;
#pragma unroll
            for (int i = 0; i < 4; ++i) {
                cp16(sb + KHo + so + i * 16, pkh + i * 16);
                cp16(sb + KLo + so + i * 16, pkl + i * 16);
                cp16(sb + VHo + so + i * 16, pvh + i * 16);
                cp16(sb + VLo + so + i * 16, pvl + i * 16);
            }
        }
        CP_COMMIT();
        CP_WAIT0();
        __syncthreads();

        float s[8][4];
#pragma unroll
        for (int nt = 0; nt < 8; ++nt)
#pragma unroll
            for (int q = 0; q < 4; ++q) s[nt][q] = 0.f;

#pragma unroll
        for (int ks = 0; ks < 4; ++ks) {
            const uint32_t ko = (uint32_t)(ks * 32);
            uint32_t kfh[8][2], kfl[8][2];
#pragma unroll
            for (int np = 0; np < 4; ++np) {
                ldm4(sb + KHo + (uint32_t)(np * 16) * ASTRIDE + b_off + ko,
                     kfh[np*2][0], kfh[np*2][1], kfh[np*2+1][0], kfh[np*2+1][1]);
                ldm4(sb + KLo + (uint32_t)(np * 16) * ASTRIDE + b_off + ko,
                     kfl[np*2][0], kfl[np*2][1], kfl[np*2+1][0], kfl[np*2+1][1]);
            }
#pragma unroll
            for (int nt = 0; nt < 8; ++nt) {
                mma16816(s[nt], qfh[ks], kfh[nt]);
                mma16816(s[nt], qfl[ks], kfh[nt]);
                mma16816(s[nt], qfh[ks], kfl[nt]);
            }
        }

        if (jt == qt) {
#pragma unroll
            for (int nt = 0; nt < 8; ++nt) {
                int kjb = jt * 64 + nt * 8 + (lane & 3) * 2;
#pragma unroll
                for (int jj = 0; jj < 2; ++jj) {
                    if (kjb + jj > qi0) s[nt][jj]     = -INFINITY;
                    if (kjb + jj > qi1) s[nt][2 + jj] = -INFINITY;
                }
            }
        }

        float rm0 = -INFINITY, rm1 = -INFINITY;
#pragma unroll
        for (int nt = 0; nt < 8; ++nt) {
            rm0 = fmaxf(rm0, fmaxf(s[nt][0], s[nt][1]));
            rm1 = fmaxf(rm1, fmaxf(s[nt][2], s[nt][3]));
        }
        rm0 = fmaxf(rm0, __shfl_xor_sync(0xffffffffu, rm0, 1));
        rm0 = fmaxf(rm0, __shfl_xor_sync(0xffffffffu, rm0, 2));
        rm1 = fmaxf(rm1, __shfl_xor_sync(0xffffffffu, rm1, 1));
        rm1 = fmaxf(rm1, __shfl_xor_sync(0xffffffffu, rm1, 2));
        float mn0 = fmaxf(m0, rm0), mn1 = fmaxf(m1, rm1);
        float al0 = __expf(m0 - mn0), al1 = __expf(m1 - mn1);
        m0 = mn0; m1 = mn1;
        float rs0 = 0.f, rs1 = 0.f;
#pragma unroll
        for (int nt = 0; nt < 8; ++nt) {
            s[nt][0] = __expf(s[nt][0] - mn0); rs0 += s[nt][0];
            s[nt][1] = __expf(s[nt][1] - mn0); rs0 += s[nt][1];
            s[nt][2] = __expf(s[nt][2] - mn1); rs1 += s[nt][2];
            s[nt][3] = __expf(s[nt][3] - mn1); rs1 += s[nt][3];
        }
        rs0 += __shfl_xor_sync(0xffffffffu, rs0, 1);
        rs0 += __shfl_xor_sync(0xffffffffu, rs0, 2);
        rs1 += __shfl_xor_sync(0xffffffffu, rs1, 1);
        rs1 += __shfl_xor_sync(0xffffffffu, rs1, 2);
        l0 = l0 * al0 + rs0;
        l1 = l1 * al1 + rs1;
#pragma unroll
        for (int nt = 0; nt < 8; ++nt) {
            oa[nt][0] *= al0; oa[nt][1] *= al0;
            oa[nt][2] *= al1; oa[nt][3] *= al1;
        }

#pragma unroll
        for (int ks = 0; ks < 4; ++ks) {
            uint32_t pah[4], pal[4];
            packhl(s[2*ks][0],   s[2*ks][1],   pah[0], pal[0]);
            packhl(s[2*ks][2],   s[2*ks][3],   pah[1], pal[1]);
            packhl(s[2*ks+1][0], s[2*ks+1][1], pah[2], pal[2]);
            packhl(s[2*ks+1][2], s[2*ks+1][3], pah[3], pal[3]);
            uint32_t vfh[8][2], vfl[8][2];
#pragma unroll
            for (int np = 0; np < 4; ++np) {
                ldm4t(sb + VHo + (uint32_t)(ks * 16) * ASTRIDE + v_off + (uint32_t)(np * 32),
                      vfh[np*2][0], vfh[np*2][1], vfh[np*2+1][0], vfh[np*2+1][1]);
                ldm4t(sb + VLo + (uint32_t)(ks * 16) * ASTRIDE + v_off + (uint32_t)(np * 32),
                      vfl[np*2][0], vfl[np*2][1], vfl[np*2+1][0], vfl[np*2+1][1]);
            }
#pragma unroll
            for (int nt = 0; nt < 8; ++nt) {
                mma16816(oa[nt], pah, vfh[nt]);
                mma16816(oa[nt], pal, vfh[nt]);
                mma16816(oa[nt], pah, vfl[nt]);
            }
        }
    }

    float inv0 = 1.f / l0, inv1 = 1.f / l1;
#pragma unroll
    for (int nt = 0; nt < 8; ++nt) {
        int col = h * HD + nt * 8 + (lane & 3) * 2;
        uint32_t hh, ll;
        packhl(oa[nt][0] * inv0, oa[nt][1] * inv0, hh, ll);
        *(uint32_t*)(Ohi + (size_t)qi0 * DMODEL + col) = hh;
        *(uint32_t*)(Olo + (size_t)qi0 * DMODEL + col) = ll;
        packhl(oa[nt][2] * inv1, oa[nt][3] * inv1, hh, ll);
        *(uint32_t*)(Ohi + (size_t)qi1 * DMODEL + col) = hh;
        *(uint32_t*)(Olo + (size_t)qi1 * DMODEL + col) = ll;
    }
}

// ---------------- host launcher ----------------------------------------------------
extern "C" void kernel_launch(void* const* d_in, const int* in_sizes, int n_in,
                              void* d_out, int out_size)
{
    const float* x_in       = (const float*)d_in[0];
    const float* conv_in_w  = (const float*)d_in[1];
    const float* conv_in_b  = (const float*)d_in[2];
    const float* ln1_w      = (const float*)d_in[3];
    const float* ln1_b      = (const float*)d_in[4];
    const float* wq         = (const float*)d_in[5];
    const float* wk         = (const float*)d_in[6];
    const float* wv         = (const float*)d_in[7];
    const float* wo         = (const float*)d_in[8];
    const float* ln2_w      = (const float*)d_in[9];
    const float* ln2_b      = (const float*)d_in[10];
    const float* w1         = (const float*)d_in[11];
    const float* b1         = (const float*)d_in[12];
    const float* w2         = (const float*)d_in[13];
    const float* b2         = (const float*)d_in[14];
    const float* w3         = (const float*)d_in[15];
    const float* b3         = (const float*)d_in[16];
    const float* conv_out_w = (const float*)d_in[17];
    const float* conv_out_b = (const float*)d_in[18];
    float* out = (float*)d_out;

    float *px, *pqkv;
    __nv_bfloat16 *pAh, *pAl, *pAh2, *pAl2, *pWh, *pWl;
    __nv_bfloat16 *pQh, *pQl, *pKh, *pKl, *pVh, *pVl;
    cudaGetSymbolAddress((void**)&px,   g_x);
    cudaGetSymbolAddress((void**)&pqkv, g_qkv);
    cudaGetSymbolAddress((void**)&pAh,  g_Ah);
    cudaGetSymbolAddress((void**)&pAl,  g_Al);
    cudaGetSymbolAddress((void**)&pAh2, g_Ah2);
    cudaGetSymbolAddress((void**)&pAl2, g_Al2);
    cudaGetSymbolAddress((void**)&pWh,  g_WBh);
    cudaGetSymbolAddress((void**)&pWl,  g_WBl);
    cudaGetSymbolAddress((void**)&pQh,  g_Qh);
    cudaGetSymbolAddress((void**)&pQl,  g_Ql);
    cudaGetSymbolAddress((void**)&pKh,  g_Kh);
    cudaGetSymbolAddress((void**)&pKl,  g_Kl);
    cudaGetSymbolAddress((void**)&pVh,  g_Vh);
    cudaGetSymbolAddress((void**)&pVl,  g_Vl);

    cudaFuncSetAttribute(attn_mma_kernel, cudaFuncAttributeMaxDynamicSharedMemorySize, AMM_SMEM);
    cudaFuncSetAttribute(gemm_bf16<false, false, false, false>, cudaFuncAttributeMaxDynamicSharedMemorySize, GSMEM_TOTAL);
    cudaFuncSetAttribute(gemm_bf16<false, false, true,  false>, cudaFuncAttributeMaxDynamicSharedMemorySize, GSMEM_TOTAL);
    cudaFuncSetAttribute(gemm_bf16<true,  true,  false, true >, cudaFuncAttributeMaxDynamicSharedMemorySize, GSMEM_TOTAL);
    cudaFuncSetAttribute(gemm_bf16<true,  false, true,  false>, cudaFuncAttributeMaxDynamicSharedMemorySize, GSMEM_TOTAL);

    conv_in_kernel<<<(SEQ * DMODEL) / 256, 256>>>(x_in, conv_in_w, conv_in_b, px);
    splitall_kernel<<<dim3(WL_ELEMS / 8 / 256, 2), 256>>>(wq, wk, wv, wo, w1, w2, w3, pWh, pWl, 0);
    splitall_kernel<<<dim3(WL_ELEMS / 8 / 256, 2), 256>>>(wq, wk, wv, wo, w1, w2, w3, pWh, pWl, 2);

    const dim3 gQKV(QKVS / 128,   SEQ / 128);
    const dim3 gD  (DMODEL / 128, SEQ / 128);
    const dim3 gF  (DFF / 128,    SEQ / 128);

    for (int i = 0; i < NLAYERS; ++i) {
        const size_t wl = (size_t)i * WL_ELEMS;
        const __nv_bfloat16* qkvh = pWh + wl;
        const __nv_bfloat16* qkvl = pWl + wl;
        const __nv_bfloat16* woh  = pWh + wl + 3 * (size_t)M1;
        const __nv_bfloat16* wol  = pWl + wl + 3 * (size_t)M1;
        const __nv_bfloat16* w1h  = pWh + wl + 4 * (size_t)M1;
        const __nv_bfloat16* w1l  = pWl + wl + 4 * (size_t)M1;
        const __nv_bfloat16* w2h  = pWh + wl + 8 * (size_t)M1;
        const __nv_bfloat16* w2l  = pWl + wl + 8 * (size_t)M1;
        const __nv_bfloat16* w3h  = pWh + wl + 24 * (size_t)M1;
        const __nv_bfloat16* w3l  = pWl + wl + 24 * (size_t)M1;

        rmsnorm_split_kernel<<<SEQ, 256>>>(px, ln1_w + i * DMODEL, ln1_b + i * DMODEL, pAh, pAl);

        gemm_bf16<false, false, false, false><<<gQKV, 128, GSMEM_TOTAL>>>(DMODEL, QKVS,
            pAh, pAl, qkvh, qkvl, nullptr, nullptr, pqkv, nullptr, nullptr);

        rope_split_kernel<<<(SEQ * NHEADS * (HD / 2)) / 256, 256>>>(pqkv,
            pQh, pQl, pKh, pKl, pVh, pVl);

        attn_mma_kernel<<<dim3(SEQ / 64, NHEADS), 128, AMM_SMEM>>>(
            pQh, pQl, pKh, pKl, pVh, pVl, pAh, pAl);

        gemm_bf16<false, false, true, false><<<gD, 128, GSMEM_TOTAL>>>(DMODEL, DMODEL,
            pAh, pAl, woh, wol, nullptr, px, px, nullptr, nullptr);

        rmsnorm_split_kernel<<<SEQ, 256>>>(px, ln2_w + i * DMODEL, ln2_b + i * DMODEL, pAh, pAl);

        gemm_bf16<true, true, false, true><<<gF, 128, GSMEM_TOTAL>>>(DMODEL, DFF,
            pAh, pAl, w1h, w1l, b1 + (size_t)i * DFF, nullptr, nullptr, pAh2, pAl2);

        gemm_bf16<true, true, false, true><<<gF, 128, GSMEM_TOTAL>>>(DFF, DFF,
            pAh2, pAl2, w2h, w2l, b2 + (size_t)i * DFF, nullptr, nullptr, pAh, pAl);

        gemm_bf16<true, false, true, false><<<gD, 128, GSMEM_TOTAL>>>(DFF, DMODEL,
            pAh, pAl, w3h, w3l, b3 + (size_t)i * DMODEL, px, px, nullptr, nullptr);
    }

    conv_out_kernel<<<dim3(SEQ, COUT), 128>>>(px, conv_out_w, conv_out_b, out);
}

// round 14
// speedup vs baseline: 1.2001x; 1.2001x over previous
#include <cuda_runtime.h>
#include <cuda_bf16.h>
#include <math.h>
#include <cstdint>

#define NLAYERS 4
#define NHEADS  16
#define DMODEL  1024
#define DFF     4096
#define KW      7
#define SEQ     2048
#define CIN     4
#define COUT    4
#define HD      64
#define QKVS    3072
#define M1      (1 << 20)
#define WL_ELEMS (28 * M1)

// ---------------- scratch ----------------------------------------------------------
__device__ float g_x  [SEQ*DMODEL];
__device__ float g_qkv[SEQ*QKVS];
__device__ __nv_bfloat16 g_Ah [SEQ*DFF];
__device__ __nv_bfloat16 g_Al [SEQ*DFF];
__device__ __nv_bfloat16 g_Ah2[SEQ*DFF];
__device__ __nv_bfloat16 g_Al2[SEQ*DFF];
__device__ __nv_bfloat16 g_WBh[NLAYERS * WL_ELEMS];
__device__ __nv_bfloat16 g_WBl[NLAYERS * WL_ELEMS];
__device__ __nv_bfloat16 g_Qh[SEQ*DMODEL];
__device__ __nv_bfloat16 g_Ql[SEQ*DMODEL];
__device__ __nv_bfloat16 g_Kh[SEQ*DMODEL];
__device__ __nv_bfloat16 g_Kl[SEQ*DMODEL];
__device__ __nv_bfloat16 g_Vh[SEQ*DMODEL];
__device__ __nv_bfloat16 g_Vl[SEQ*DMODEL];

__device__ __forceinline__ uint32_t smem_u32(const void* p) {
    uint32_t a;
    asm("{ .reg .u64 t; cvta.to.shared.u64 t, %1; cvt.u32.u64 %0, t; }" : "=r"(a) : "l"(p));
    return a;
}

__device__ __forceinline__ void packhl(float x, float y, uint32_t& hi, uint32_t& lo) {
    __nv_bfloat16 hx = __float2bfloat16(x), hy = __float2bfloat16(y);
    __nv_bfloat16 lx = __float2bfloat16(x - __bfloat162float(hx));
    __nv_bfloat16 ly = __float2bfloat16(y - __bfloat162float(hy));
    hi = (uint32_t)__bfloat16_as_ushort(hx) | ((uint32_t)__bfloat16_as_ushort(hy) << 16);
    lo = (uint32_t)__bfloat16_as_ushort(lx) | ((uint32_t)__bfloat16_as_ushort(ly) << 16);
}

// ---------------- split ALL weights: coalesced + high MLP --------------------------
// Block owns 16384 contiguous elems (divides 2^20, so single src region).
// Thread handles 8 sub-chunks of 8 elems strided by 2048 elems; all loads first.
__global__ void __launch_bounds__(256) splitall_kernel(
    const float* __restrict__ wq, const float* __restrict__ wk, const float* __restrict__ wv,
    const float* __restrict__ wo, const float* __restrict__ w1, const float* __restrict__ w2,
    const float* __restrict__ w3,
    __nv_bfloat16* __restrict__ dh, __nv_bfloat16* __restrict__ dl)
{
    const int layer = blockIdx.y;
    const size_t base = (size_t)blockIdx.x * 16384;
    const float* src;
    if (base < 3 * (size_t)M1) {
        const float* t = (base < (size_t)M1) ? wq : (base < 2 * (size_t)M1) ? wk : wv;
        src = t + (size_t)layer * M1 + (base & (M1 - 1));
    } else if (base < 4 * (size_t)M1) {
        src = wo + (size_t)layer * M1 + (base - 3 * (size_t)M1);
    } else if (base < 8 * (size_t)M1) {
        src = w1 + (size_t)layer * 4 * M1 + (base - 4 * (size_t)M1);
    } else if (base < 24 * (size_t)M1) {
        src = w2 + (size_t)layer * 16 * M1 + (base - 8 * (size_t)M1);
    } else {
        src = w3 + (size_t)layer * 4 * M1 + (base - 24 * (size_t)M1);
    }
    const int tid = threadIdx.x;
    float4 v[16];
#pragma unroll
    for (int it = 0; it < 8; ++it) {
        const float* p = src + it * 2048 + tid * 8;
        v[2 * it]     = *(const float4*)p;
        v[2 * it + 1] = *(const float4*)(p + 4);
    }
    __nv_bfloat16* oh = dh + (size_t)layer * WL_ELEMS + base;
    __nv_bfloat16* ol = dl + (size_t)layer * WL_ELEMS + base;
#pragma unroll
    for (int it = 0; it < 8; ++it) {
        const int o = it * 2048 + tid * 8;
        uint2 ph0, pl0, ph1, pl1;
        packhl(v[2*it].x,   v[2*it].y,   ph0.x, pl0.x);
        packhl(v[2*it].z,   v[2*it].w,   ph0.y, pl0.y);
        packhl(v[2*it+1].x, v[2*it+1].y, ph1.x, pl1.x);
        packhl(v[2*it+1].z, v[2*it+1].w, ph1.y, pl1.y);
        *(uint2*)(oh + o)     = ph0;
        *(uint2*)(ol + o)     = pl0;
        *(uint2*)(oh + o + 4) = ph1;
        *(uint2*)(ol + o + 4) = pl1;
    }
}

// ================= bf16 HMMA GEMM: round-8/11 validated config ====================
#define GSTRIDE 80
#define AH_OFF 0
#define AL_OFF 10240
#define BH_OFF 20480
#define BL_OFF 30720
#define STAGE_SZ 40960
#define GSMEM_TOTAL (2 * STAGE_SZ)

__device__ __forceinline__ void ldm4(uint32_t addr, uint32_t& r0, uint32_t& r1,
                                     uint32_t& r2, uint32_t& r3) {
    asm volatile("ldmatrix.sync.aligned.m8n8.x4.shared.b16 {%0,%1,%2,%3}, [%4];"
                 : "=r"(r0), "=r"(r1), "=r"(r2), "=r"(r3) : "r"(addr));
}
__device__ __forceinline__ void ldm4t(uint32_t addr, uint32_t& r0, uint32_t& r1,
                                      uint32_t& r2, uint32_t& r3) {
    asm volatile("ldmatrix.sync.aligned.m8n8.x4.trans.shared.b16 {%0,%1,%2,%3}, [%4];"
                 : "=r"(r0), "=r"(r1), "=r"(r2), "=r"(r3) : "r"(addr));
}
__device__ __forceinline__ void mma16816(float* c, const uint32_t* a, const uint32_t* b) {
    asm volatile(
        "mma.sync.aligned.m16n8k16.row.col.f32.bf16.bf16.f32 "
        "{%0,%1,%2,%3}, {%4,%5,%6,%7}, {%8,%9}, {%0,%1,%2,%3};"
        : "+f"(c[0]), "+f"(c[1]), "+f"(c[2]), "+f"(c[3])
        : "r"(a[0]), "r"(a[1]), "r"(a[2]), "r"(a[3]), "r"(b[0]), "r"(b[1]));
}
__device__ __forceinline__ void cp16(uint32_t saddr, const void* gaddr) {
    asm volatile("cp.async.cg.shared.global [%0], [%1], 16;" :: "r"(saddr), "l"(gaddr));
}
#define CP_COMMIT() asm volatile("cp.async.commit_group;" ::: "memory")
#define CP_WAIT0()  asm volatile("cp.async.wait_group 0;" ::: "memory")

template<bool BIAS, bool RELU, bool RES, bool OSPLIT>
__global__ void __launch_bounds__(256, 2)
gemm_bf16(int K, int N,
          const __nv_bfloat16* __restrict__ Ah, const __nv_bfloat16* __restrict__ Al,
          const __nv_bfloat16* __restrict__ Bh, const __nv_bfloat16* __restrict__ Bl,
          const float* __restrict__ bias, const float* __restrict__ res,
          float* __restrict__ C,
          __nv_bfloat16* __restrict__ Chi, __nv_bfloat16* __restrict__ Clo)
{
    extern __shared__ __align__(128) char smem[];
    const uint32_t sb = smem_u32(smem);
    const int tid  = threadIdx.x;
    const int wid  = tid >> 5;
    const int lane = tid & 31;
    const int wm   = wid >> 2;
    const int wn   = wid & 3;
    const int m0   = blockIdx.y * 128;
    const int n0   = blockIdx.x * 128;

    float acc[4][4][4];
#pragma unroll
    for (int i = 0; i < 4; ++i)
#pragma unroll
        for (int j = 0; j < 4; ++j)
#pragma unroll
            for (int q = 0; q < 4; ++q) acc[i][j][q] = 0.0f;

    const int NC = K >> 5;
    const int lrow = tid >> 1;
    const int lqb  = (tid & 1) * 32;

    const int sub = lane >> 3, r8 = lane & 7;
    const uint32_t a_lane_off = (uint32_t)(((sub & 1) * 8 + r8) * GSTRIDE + ((sub >> 1) * 8) * 2);
    const uint32_t b_lane_off = (uint32_t)((((sub >> 1) * 8) + r8) * GSTRIDE + ((sub & 1) * 8) * 2);

    auto issue = [&](int c) {
        const uint32_t stg  = sb + (uint32_t)(c & 1) * STAGE_SZ;
        const uint32_t soff = (uint32_t)(lrow * GSTRIDE + lqb);
        const size_t   goff = (size_t)lrow * K + (size_t)c * 32;
        const char* ah = (const char*)(Ah + (size_t)m0 * K + goff) + lqb;
        const char* al = (const char*)(Al + (size_t)m0 * K + goff) + lqb;
        const char* bh = (const char*)(Bh + (size_t)n0 * K + goff) + lqb;
        const char* bl = (const char*)(Bl + (size_t)n0 * K + goff) + lqb;
        cp16(stg + AH_OFF + soff, ah);       cp16(stg + AH_OFF + soff + 16, ah + 16);
        cp16(stg + AL_OFF + soff, al);       cp16(stg + AL_OFF + soff + 16, al + 16);
        cp16(stg + BH_OFF + soff, bh);       cp16(stg + BH_OFF + soff + 16, bh + 16);
        cp16(stg + BL_OFF + soff, bl);       cp16(stg + BL_OFF + soff + 16, bl + 16);
    };

    issue(0); CP_COMMIT();

    for (int c = 0; c < NC; ++c) {
        CP_WAIT0();
        __syncthreads();
        if (c + 1 < NC) { issue(c + 1); CP_COMMIT(); }

        const uint32_t stg  = sb + (uint32_t)(c & 1) * STAGE_SZ;
        const uint32_t ah_b = stg + AH_OFF + (uint32_t)(wm * 64) * GSTRIDE + a_lane_off;
        const uint32_t al_b = stg + AL_OFF + (uint32_t)(wm * 64) * GSTRIDE + a_lane_off;
        const uint32_t bh_b = stg + BH_OFF + (uint32_t)(wn * 32) * GSTRIDE + b_lane_off;
        const uint32_t bl_b = stg + BL_OFF + (uint32_t)(wn * 32) * GSTRIDE + b_lane_off;

#pragma unroll
        for (int ks = 0; ks < 2; ++ks) {
            const uint32_t ko = (uint32_t)(ks * 32);
            uint32_t ahh[4][4], bhh[4][2];
#pragma unroll
            for (int mt = 0; mt < 4; ++mt)
                ldm4(ah_b + (uint32_t)(mt * 16) * GSTRIDE + ko,
                     ahh[mt][0], ahh[mt][1], ahh[mt][2], ahh[mt][3]);
#pragma unroll
            for (int np = 0; np < 2; ++np)
                ldm4(bh_b + (uint32_t)(np * 16) * GSTRIDE + ko,
                     bhh[np*2][0], bhh[np*2][1], bhh[np*2+1][0], bhh[np*2+1][1]);
#pragma unroll
            for (int mt = 0; mt < 4; ++mt)
#pragma unroll
                for (int nt = 0; nt < 4; ++nt)
                    mma16816(acc[mt][nt], ahh[mt], bhh[nt]);
            {
                uint32_t bhl[4][2];
#pragma unroll
                for (int np = 0; np < 2; ++np)
                    ldm4(bl_b + (uint32_t)(np * 16) * GSTRIDE + ko,
                         bhl[np*2][0], bhl[np*2][1], bhl[np*2+1][0], bhl[np*2+1][1]);
#pragma unroll
                for (int mt = 0; mt < 4; ++mt)
#pragma unroll
                    for (int nt = 0; nt < 4; ++nt)
                        mma16816(acc[mt][nt], ahh[mt], bhl[nt]);
            }
            {
                uint32_t ahl[4][4];
#pragma unroll
                for (int mt = 0; mt < 4; ++mt)
                    ldm4(al_b + (uint32_t)(mt * 16) * GSTRIDE + ko,
                         ahl[mt][0], ahl[mt][1], ahl[mt][2], ahl[mt][3]);
#pragma unroll
                for (int mt = 0; mt < 4; ++mt)
#pragma unroll
                    for (int nt = 0; nt < 4; ++nt)
                        mma16816(acc[mt][nt], ahl[mt], bhh[nt]);
            }
        }
        __syncthreads();
    }

    const int erow = m0 + wm * 64 + (lane >> 2);
    const int ecol = n0 + wn * 32 + (lane & 3) * 2;
#pragma unroll
    for (int mt = 0; mt < 4; ++mt) {
#pragma unroll
        for (int nt = 0; nt < 4; ++nt) {
            const int r0 = erow + mt * 16;
            const int cc = ecol + nt * 8;
            float2 v0 = make_float2(acc[mt][nt][0], acc[mt][nt][1]);
            float2 v1 = make_float2(acc[mt][nt][2], acc[mt][nt][3]);
            if (BIAS) {
                float2 bb = *(const float2*)(bias + cc);
                v0.x += bb.x; v0.y += bb.y; v1.x += bb.x; v1.y += bb.y;
            }
            if (RELU) {
                v0.x = fmaxf(v0.x, 0.f); v0.y = fmaxf(v0.y, 0.f);
                v1.x = fmaxf(v1.x, 0.f); v1.y = fmaxf(v1.y, 0.f);
            }
            if (RES) {
                float2 r4 = *(const float2*)(res + (size_t)r0 * N + cc);
                v0.x += r4.x; v0.y += r4.y;
                float2 r5 = *(const float2*)(res + (size_t)(r0 + 8) * N + cc);
                v1.x += r5.x; v1.y += r5.y;
            }
            if (OSPLIT) {
                uint32_t h0, l0, h1, l1;
                packhl(v0.x, v0.y, h0, l0);
                packhl(v1.x, v1.y, h1, l1);
                *(uint32_t*)(Chi + (size_t)r0 * N + cc) = h0;
                *(uint32_t*)(Clo + (size_t)r0 * N + cc) = l0;
                *(uint32_t*)(Chi + (size_t)(r0 + 8) * N + cc) = h1;
                *(uint32_t*)(Clo + (size_t)(r0 + 8) * N + cc) = l1;
            } else {
                *(float2*)(C + (size_t)r0 * N + cc) = v0;
                *(float2*)(C + (size_t)(r0 + 8) * N + cc) = v1;
            }
        }
    }
}

// ---------------- conv_in ----------------------------------------------------------
__global__ void conv_in_kernel(const float* __restrict__ x,
                               const float* __restrict__ w,
                               const float* __restrict__ b,
                               float* __restrict__ h)
{
    int idx = blockIdx.x * blockDim.x + threadIdx.x;
    if (idx >= SEQ * DMODEL) return;
    int d = idx & (DMODEL - 1);
    int l = idx >> 10;
    float acc = b[d];
#pragma unroll
    for (int c = 0; c < CIN; ++c) {
#pragma unroll
        for (int t = 0; t < KW; ++t) {
            int lt = l + t - (KW - 1);
            if (lt >= 0) acc += w[(d * CIN + c) * KW + t] * x[c * SEQ + lt];
        }
    }
    h[idx] = fmaxf(acc, 0.0f);
}

// ---------------- conv_out ---------------------------------------------------------
__global__ void conv_out_kernel(const float* __restrict__ xb,
                                const float* __restrict__ w,
                                const float* __restrict__ b,
                                float* __restrict__ out)
{
    int l  = blockIdx.x;
    int co = blockIdx.y;
    float acc = 0.0f;
    for (int d = threadIdx.x; d < DMODEL; d += 128) {
        const float* wp = w + (size_t)(co * DMODEL + d) * KW;
#pragma unroll
        for (int t = 0; t < KW; ++t) {
            int lt = l + t - (KW - 1);
            if (lt >= 0) acc += wp[t] * xb[(size_t)lt * DMODEL + d];
        }
    }
#pragma unroll
    for (int s = 16; s >= 1; s >>= 1) acc += __shfl_xor_sync(0xffffffffu, acc, s);
    __shared__ float red[4];
    if ((threadIdx.x & 31) == 0) red[threadIdx.x >> 5] = acc;
    __syncthreads();
    if (threadIdx.x == 0)
        out[co * SEQ + l] = red[0] + red[1] + red[2] + red[3] + b[co];
}

// ---------------- RMSNorm -> hi/lo split -------------------------------------------
__global__ void __launch_bounds__(256) rmsnorm_split_kernel(const float* __restrict__ x,
                                                            const float* __restrict__ w,
                                                            const float* __restrict__ b,
                                                            __nv_bfloat16* __restrict__ hi,
                                                            __nv_bfloat16* __restrict__ lo)
{
    int l = blockIdx.x;
    const float* xr = x + (size_t)l * DMODEL;
    const int tid = threadIdx.x;
    float4 v = *(const float4*)(xr + tid * 4);
    float ss = v.x * v.x + v.y * v.y + v.z * v.z + v.w * v.w;
#pragma unroll
    for (int s = 16; s >= 1; s >>= 1) ss += __shfl_xor_sync(0xffffffffu, ss, s);
    __shared__ float red[8];
    __shared__ float sinv;
    if ((tid & 31) == 0) red[tid >> 5] = ss;
    __syncthreads();
    if (tid == 0) {
        float t = 0.0f;
#pragma unroll
        for (int i = 0; i < 8; ++i) t += red[i];
        sinv = rsqrtf(t * (1.0f / DMODEL) + 1e-5f);
    }
    __syncthreads();
    float inv = sinv;
    float4 wv = *(const float4*)(w + tid * 4);
    float4 bv = *(const float4*)(b + tid * 4);
    float y0 = v.x * inv * wv.x + bv.x;
    float y1 = v.y * inv * wv.y + bv.y;
    float y2 = v.z * inv * wv.z + bv.z;
    float y3 = v.w * inv * wv.w + bv.w;
    uint2 ph, pl;
    packhl(y0, y1, ph.x, pl.x);
    packhl(y2, y3, ph.y, pl.y);
    *(uint2*)(hi + (size_t)l * DMODEL + tid * 4) = ph;
    *(uint2*)(lo + (size_t)l * DMODEL + tid * 4) = pl;
}

// ---------------- RoPE + split -----------------------------------------------------
__device__ __forceinline__ void split1(float x, __nv_bfloat16* hi, __nv_bfloat16* lo, size_t o) {
    __nv_bfloat16 h = __float2bfloat16(x);
    hi[o] = h;
    lo[o] = __float2bfloat16(x - __bfloat162float(h));
}

__global__ void rope_split_kernel(const float* __restrict__ qkv,
                                  __nv_bfloat16* __restrict__ Qh, __nv_bfloat16* __restrict__ Ql,
                                  __nv_bfloat16* __restrict__ Kh, __nv_bfloat16* __restrict__ Kl,
                                  __nv_bfloat16* __restrict__ Vh, __nv_bfloat16* __restrict__ Vl)
{
    int idx = blockIdx.x * blockDim.x + threadIdx.x;
    if (idx >= SEQ * NHEADS * (HD / 2)) return;
    int j = idx & 31;
    int h = (idx >> 5) & (NHEADS - 1);
    int l = idx >> 9;
    float inv_freq = exp2f(-(float)j * (13.287712379549449f / 32.0f));
    float ang = (float)l * inv_freq;
    float s, c;
    sincosf(ang, &s, &c);
    size_t ib = (size_t)l * QKVS + h * HD + j;
    size_t ob = (size_t)l * DMODEL + h * HD + j;
    float q1 = qkv[ib], q2 = qkv[ib + 32];
    split1((q1 * c - q2 * s) * 0.125f, Qh, Ql, ob);
    split1((q2 * c + q1 * s) * 0.125f, Qh, Ql, ob + 32);
    float k1 = qkv[ib + DMODEL], k2 = qkv[ib + DMODEL + 32];
    split1(k1 * c - k2 * s, Kh, Kl, ob);
    split1(k2 * c + k1 * s, Kh, Kl, ob + 32);
    split1(qkv[ib + 2 * DMODEL], Vh, Vl, ob);
    split1(qkv[ib + 2 * DMODEL + 32], Vh, Vl, ob + 32);
}

// ---------------- MMA flash attention (bf16 3-term, fp32 softmax) ------------------
#define ASTRIDE 144
#define AMM_SMEM (6 * 64 * ASTRIDE)

__global__ void __launch_bounds__(128) attn_mma_kernel(
    const __nv_bfloat16* __restrict__ Qh, const __nv_bfloat16* __restrict__ Ql,
    const __nv_bfloat16* __restrict__ Kh, const __nv_bfloat16* __restrict__ Kl,
    const __nv_bfloat16* __restrict__ Vh, const __nv_bfloat16* __restrict__ Vl,
    __nv_bfloat16* __restrict__ Ohi, __nv_bfloat16* __restrict__ Olo)
{
    extern __shared__ __align__(128) char smem[];
    const uint32_t sb = smem_u32(smem);
    const int h  = blockIdx.y;
    const int qt = blockIdx.x;
    const int q0 = qt * 64;
    const int tid = threadIdx.x, wid = tid >> 5, lane = tid & 31;

    const uint32_t QHo = 0, QLo = 9216, KHo = 18432, KLo = 27648, VHo = 36864, VLo = 46080;

    {
        const int row = tid >> 1, ho = (tid & 1) * 64;
        const uint32_t so = (uint32_t)(row * ASTRIDE + ho);
        const char* gh = (const char*)(Qh + (size_t)(q0 + row) * DMODEL + h * HD) + ho;
        const char* gl = (const char*)(Ql + (size_t)(q0 + row) * DMODEL + h * HD) + ho;
#pragma unroll
        for (int i = 0; i < 4; ++i) {
            cp16(sb + QHo + so + i * 16, gh + i * 16);
            cp16(sb + QLo + so + i * 16, gl + i * 16);
        }
    }
    CP_COMMIT();
    CP_WAIT0();
    __syncthreads();

    const int sub = lane >> 3, r8v = lane & 7;
    const uint32_t a_off = (uint32_t)(((sub & 1) * 8 + r8v) * ASTRIDE + ((sub >> 1) * 8) * 2);
    const uint32_t b_off = (uint32_t)((((sub >> 1) * 8) + r8v) * ASTRIDE + (sub & 1) * 16);
    const uint32_t v_off = (uint32_t)(((sub & 1) * 8 + r8v) * ASTRIDE + (sub >> 1) * 16);

    uint32_t qfh[4][4], qfl[4][4];
#pragma unroll
    for (int ks = 0; ks < 4; ++ks) {
        ldm4(sb + QHo + (uint32_t)(wid * 16) * ASTRIDE + a_off + (uint32_t)(ks * 32),
             qfh[ks][0], qfh[ks][1], qfh[ks][2], qfh[ks][3]);
        ldm4(sb + QLo + (uint32_t)(wid * 16) * ASTRIDE + a_off + (uint32_t)(ks * 32),
             qfl[ks][0], qfl[ks][1], qfl[ks][2], qfl[ks][3]);
    }

    float m0 = -INFINITY, m1 = -INFINITY, l0 = 0.f, l1 = 0.f;
    float oa[8][4];
#pragma unroll
    for (int nt = 0; nt < 8; ++nt)
#pragma unroll
        for (int q = 0; q < 4; ++q) oa[nt][q] = 0.f;

    const int qi0 = q0 + wid * 16 + (lane >> 2);
    const int qi1 = qi0 + 8;

    for (int jt = 0; jt <= qt; ++jt) {
        __syncthreads();
        {
            const int row = tid >> 1, ho = (tid & 1) * 64;
            const uint32_t so = (uint32_t)(row * ASTRIDE + ho);
            const size_t g = (size_t)(jt * 64 + row) * DMODEL + h * HD;
            const char* pkh = (const char*)(Kh + g) + ho;
            const char* pkl = (const char*)(Kl + g) + ho;
            const char* pvh = (const char*)(Vh + g) + ho;
            const char* pvl = (const char*)(Vl + g) + ho;
#pragma unroll
            for (int i = 0; i < 4; ++i) {
                cp16(sb + KHo + so + i * 16, pkh + i * 16);
                cp16(sb + KLo + so + i * 16, pkl + i * 16);
                cp16(sb + VHo + so + i * 16, pvh + i * 16);
                cp16(sb + VLo + so + i * 16, pvl + i * 16);
            }
        }
        CP_COMMIT();
        CP_WAIT0();
        __syncthreads();

        float s[8][4];
#pragma unroll
        for (int nt = 0; nt < 8; ++nt)
#pragma unroll
            for (int q = 0; q < 4; ++q) s[nt][q] = 0.f;

#pragma unroll
        for (int ks = 0; ks < 4; ++ks) {
            const uint32_t ko = (uint32_t)(ks * 32);
            uint32_t kfh[8][2], kfl[8][2];
#pragma unroll
            for (int np = 0; np < 4; ++np) {
                ldm4(sb + KHo + (uint32_t)(np * 16) * ASTRIDE + b_off + ko,
                     kfh[np*2][0], kfh[np*2][1], kfh[np*2+1][0], kfh[np*2+1][1]);
                ldm4(sb + KLo + (uint32_t)(np * 16) * ASTRIDE + b_off + ko,
                     kfl[np*2][0], kfl[np*2][1], kfl[np*2+1][0], kfl[np*2+1][1]);
            }
#pragma unroll
            for (int nt = 0; nt < 8; ++nt) {
                mma16816(s[nt], qfh[ks], kfh[nt]);
                mma16816(s[nt], qfl[ks], kfh[nt]);
                mma16816(s[nt], qfh[ks], kfl[nt]);
            }
        }

        if (jt == qt) {
#pragma unroll
            for (int nt = 0; nt < 8; ++nt) {
                int kjb = jt * 64 + nt * 8 + (lane & 3) * 2;
#pragma unroll
                for (int jj = 0; jj < 2; ++jj) {
                    if (kjb + jj > qi0) s[nt][jj]     = -INFINITY;
                    if (kjb + jj > qi1) s[nt][2 + jj] = -INFINITY;
                }
            }
        }

        float rm0 = -INFINITY, rm1 = -INFINITY;
#pragma unroll
        for (int nt = 0; nt < 8; ++nt) {
            rm0 = fmaxf(rm0, fmaxf(s[nt][0], s[nt][1]));
            rm1 = fmaxf(rm1, fmaxf(s[nt][2], s[nt][3]));
        }
        rm0 = fmaxf(rm0, __shfl_xor_sync(0xffffffffu, rm0, 1));
        rm0 = fmaxf(rm0, __shfl_xor_sync(0xffffffffu, rm0, 2));
        rm1 = fmaxf(rm1, __shfl_xor_sync(0xffffffffu, rm1, 1));
        rm1 = fmaxf(rm1, __shfl_xor_sync(0xffffffffu, rm1, 2));
        float mn0 = fmaxf(m0, rm0), mn1 = fmaxf(m1, rm1);
        float al0 = __expf(m0 - mn0), al1 = __expf(m1 - mn1);
        m0 = mn0; m1 = mn1;
        float rs0 = 0.f, rs1 = 0.f;
#pragma unroll
        for (int nt = 0; nt < 8; ++nt) {
            s[nt][0] = __expf(s[nt][0] - mn0); rs0 += s[nt][0];
            s[nt][1] = __expf(s[nt][1] - mn0); rs0 += s[nt][1];
            s[nt][2] = __expf(s[nt][2] - mn1); rs1 += s[nt][2];
            s[nt][3] = __expf(s[nt][3] - mn1); rs1 += s[nt][3];
        }
        rs0 += __shfl_xor_sync(0xffffffffu, rs0, 1);
        rs0 += __shfl_xor_sync(0xffffffffu, rs0, 2);
        rs1 += __shfl_xor_sync(0xffffffffu, rs1, 1);
        rs1 += __shfl_xor_sync(0xffffffffu, rs1, 2);
        l0 = l0 * al0 + rs0;
        l1 = l1 * al1 + rs1;
#pragma unroll
        for (int nt = 0; nt < 8; ++nt) {
            oa[nt][0] *= al0; oa[nt][1] *= al0;
            oa[nt][2] *= al1; oa[nt][3] *= al1;
        }

#pragma unroll
        for (int ks = 0; ks < 4; ++ks) {
            uint32_t pah[4], pal[4];
            packhl(s[2*ks][0],   s[2*ks][1],   pah[0], pal[0]);
            packhl(s[2*ks][2],   s[2*ks][3],   pah[1], pal[1]);
            packhl(s[2*ks+1][0], s[2*ks+1][1], pah[2], pal[2]);
            packhl(s[2*ks+1][2], s[2*ks+1][3], pah[3], pal[3]);
            uint32_t vfh[8][2], vfl[8][2];
#pragma unroll
            for (int np = 0; np < 4; ++np) {
                ldm4t(sb + VHo + (uint32_t)(ks * 16) * ASTRIDE + v_off + (uint32_t)(np * 32),
                      vfh[np*2][0], vfh[np*2][1], vfh[np*2+1][0], vfh[np*2+1][1]);
                ldm4t(sb + VLo + (uint32_t)(ks * 16) * ASTRIDE + v_off + (uint32_t)(np * 32),
                      vfl[np*2][0], vfl[np*2][1], vfl[np*2+1][0], vfl[np*2+1][1]);
            }
#pragma unroll
            for (int nt = 0; nt < 8; ++nt) {
                mma16816(oa[nt], pah, vfh[nt]);
                mma16816(oa[nt], pal, vfh[nt]);
                mma16816(oa[nt], pah, vfl[nt]);
            }
        }
    }

    float inv0 = 1.f / l0, inv1 = 1.f / l1;
#pragma unroll
    for (int nt = 0; nt < 8; ++nt) {
        int col = h * HD + nt * 8 + (lane & 3) * 2;
        uint32_t hh, ll;
        packhl(oa[nt][0] * inv0, oa[nt][1] * inv0, hh, ll);
        *(uint32_t*)(Ohi + (size_t)qi0 * DMODEL + col) = hh;
        *(uint32_t*)(Olo + (size_t)qi0 * DMODEL + col) = ll;
        packhl(oa[nt][2] * inv1, oa[nt][3] * inv1, hh, ll);
        *(uint32_t*)(Ohi + (size_t)qi1 * DMODEL + col) = hh;
        *(uint32_t*)(Olo + (size_t)qi1 * DMODEL + col) = ll;
    }
}

// ---------------- host launcher ----------------------------------------------------
extern "C" void kernel_launch(void* const* d_in, const int* in_sizes, int n_in,
                              void* d_out, int out_size)
{
    const float* x_in       = (const float*)d_in[0];
    const float* conv_in_w  = (const float*)d_in[1];
    const float* conv_in_b  = (const float*)d_in[2];
    const float* ln1_w      = (const float*)d_in[3];
    const float* ln1_b      = (const float*)d_in[4];
    const float* wq         = (const float*)d_in[5];
    const float* wk         = (const float*)d_in[6];
    const float* wv         = (const float*)d_in[7];
    const float* wo         = (const float*)d_in[8];
    const float* ln2_w      = (const float*)d_in[9];
    const float* ln2_b      = (const float*)d_in[10];
    const float* w1         = (const float*)d_in[11];
    const float* b1         = (const float*)d_in[12];
    const float* w2         = (const float*)d_in[13];
    const float* b2         = (const float*)d_in[14];
    const float* w3         = (const float*)d_in[15];
    const float* b3         = (const float*)d_in[16];
    const float* conv_out_w = (const float*)d_in[17];
    const float* conv_out_b = (const float*)d_in[18];
    float* out = (float*)d_out;

    float *px, *pqkv;
    __nv_bfloat16 *pAh, *pAl, *pAh2, *pAl2, *pWh, *pWl;
    __nv_bfloat16 *pQh, *pQl, *pKh, *pKl, *pVh, *pVl;
    cudaGetSymbolAddress((void**)&px,   g_x);
    cudaGetSymbolAddress((void**)&pqkv, g_qkv);
    cudaGetSymbolAddress((void**)&pAh,  g_Ah);
    cudaGetSymbolAddress((void**)&pAl,  g_Al);
    cudaGetSymbolAddress((void**)&pAh2, g_Ah2);
    cudaGetSymbolAddress((void**)&pAl2, g_Al2);
    cudaGetSymbolAddress((void**)&pWh,  g_WBh);
    cudaGetSymbolAddress((void**)&pWl,  g_WBl);
    cudaGetSymbolAddress((void**)&pQh,  g_Qh);
    cudaGetSymbolAddress((void**)&pQl,  g_Ql);
    cudaGetSymbolAddress((void**)&pKh,  g_Kh);
    cudaGetSymbolAddress((void**)&pKl,  g_Kl);
    cudaGetSymbolAddress((void**)&pVh,  g_Vh);
    cudaGetSymbolAddress((void**)&pVl,  g_Vl);

    cudaFuncSetAttribute(attn_mma_kernel, cudaFuncAttributeMaxDynamicSharedMemorySize, AMM_SMEM);
    cudaFuncSetAttribute(gemm_bf16<false, false, false, false>, cudaFuncAttributeMaxDynamicSharedMemorySize, GSMEM_TOTAL);
    cudaFuncSetAttribute(gemm_bf16<false, false, true,  false>, cudaFuncAttributeMaxDynamicSharedMemorySize, GSMEM_TOTAL);
    cudaFuncSetAttribute(gemm_bf16<true,  true,  false, true >, cudaFuncAttributeMaxDynamicSharedMemorySize, GSMEM_TOTAL);
    cudaFuncSetAttribute(gemm_bf16<true,  false, true,  false>, cudaFuncAttributeMaxDynamicSharedMemorySize, GSMEM_TOTAL);

    conv_in_kernel<<<(SEQ * DMODEL) / 256, 256>>>(x_in, conv_in_w, conv_in_b, px);
    splitall_kernel<<<dim3(WL_ELEMS / 16384, NLAYERS), 256>>>(wq, wk, wv, wo, w1, w2, w3, pWh, pWl);

    const dim3 gQKV(QKVS / 128,   SEQ / 128);
    const dim3 gD  (DMODEL / 128, SEQ / 128);
    const dim3 gF  (DFF / 128,    SEQ / 128);

    for (int i = 0; i < NLAYERS; ++i) {
        const size_t wl = (size_t)i * WL_ELEMS;
        const __nv_bfloat16* qkvh = pWh + wl;
        const __nv_bfloat16* qkvl = pWl + wl;
        const __nv_bfloat16* woh  = pWh + wl + 3 * (size_t)M1;
        const __nv_bfloat16* wol  = pWl + wl + 3 * (size_t)M1;
        const __nv_bfloat16* w1h  = pWh + wl + 4 * (size_t)M1;
        const __nv_bfloat16* w1l  = pWl + wl + 4 * (size_t)M1;
        const __nv_bfloat16* w2h  = pWh + wl + 8 * (size_t)M1;
        const __nv_bfloat16* w2l  = pWl + wl + 8 * (size_t)M1;
        const __nv_bfloat16* w3h  = pWh + wl + 24 * (size_t)M1;
        const __nv_bfloat16* w3l  = pWl + wl + 24 * (size_t)M1;

        rmsnorm_split_kernel<<<SEQ, 256>>>(px, ln1_w + i * DMODEL, ln1_b + i * DMODEL, pAh, pAl);

        gemm_bf16<false, false, false, false><<<gQKV, 256, GSMEM_TOTAL>>>(DMODEL, QKVS,
            pAh, pAl, qkvh, qkvl, nullptr, nullptr, pqkv, nullptr, nullptr);

        rope_split_kernel<<<(SEQ * NHEADS * (HD / 2)) / 256, 256>>>(pqkv,
            pQh, pQl, pKh, pKl, pVh, pVl);

        attn_mma_kernel<<<dim3(SEQ / 64, NHEADS), 128, AMM_SMEM>>>(
            pQh, pQl, pKh, pKl, pVh, pVl, pAh, pAl);

        gemm_bf16<false, false, true, false><<<gD, 256, GSMEM_TOTAL>>>(DMODEL, DMODEL,
            pAh, pAl, woh, wol, nullptr, px, px, nullptr, nullptr);

        rmsnorm_split_kernel<<<SEQ, 256>>>(px, ln2_w + i * DMODEL, ln2_b + i * DMODEL, pAh, pAl);

        gemm_bf16<true, true, false, true><<<gF, 256, GSMEM_TOTAL>>>(DMODEL, DFF,
            pAh, pAl, w1h, w1l, b1 + (size_t)i * DFF, nullptr, nullptr, pAh2, pAl2);

        gemm_bf16<true, true, false, true><<<gF, 256, GSMEM_TOTAL>>>(DFF, DFF,
            pAh2, pAl2, w2h, w2l, b2 + (size_t)i * DFF, nullptr, nullptr, pAh, pAl);

        gemm_bf16<true, false, true, false><<<gD, 256, GSMEM_TOTAL>>>(DFF, DMODEL,
            pAh, pAl, w3h, w3l, b3 + (size_t)i * DMODEL, px, px, nullptr, nullptr);
    }

    conv_out_kernel<<<dim3(SEQ, COUT), 128>>>(px, conv_out_w, conv_out_b, out);
}

// round 15
// speedup vs baseline: 1.2240x; 1.0199x over previous
#include <cuda_runtime.h>
#include <cuda_bf16.h>
#include <math.h>
#include <cstdint>

#define NLAYERS 4
#define NHEADS  16
#define DMODEL  1024
#define DFF     4096
#define KW      7
#define SEQ     2048
#define CIN     4
#define COUT    4
#define HD      64
#define QKVS    3072
#define M1      (1 << 20)
#define WL_ELEMS (28 * M1)

// ---------------- scratch ----------------------------------------------------------
__device__ float g_x  [SEQ*DMODEL];
__device__ float g_qkv[SEQ*QKVS];          // also reused as K-split partial buffers
__device__ __nv_bfloat16 g_Ah [SEQ*DFF];
__device__ __nv_bfloat16 g_Al [SEQ*DFF];
__device__ __nv_bfloat16 g_Ah2[SEQ*DFF];
__device__ __nv_bfloat16 g_Al2[SEQ*DFF];
__device__ __nv_bfloat16 g_WBh[NLAYERS * WL_ELEMS];
__device__ __nv_bfloat16 g_WBl[NLAYERS * WL_ELEMS];
__device__ __nv_bfloat16 g_Qh[SEQ*DMODEL];
__device__ __nv_bfloat16 g_Ql[SEQ*DMODEL];
__device__ __nv_bfloat16 g_Kh[SEQ*DMODEL];
__device__ __nv_bfloat16 g_Kl[SEQ*DMODEL];
__device__ __nv_bfloat16 g_Vh[SEQ*DMODEL];
__device__ __nv_bfloat16 g_Vl[SEQ*DMODEL];

__device__ __forceinline__ uint32_t smem_u32(const void* p) {
    uint32_t a;
    asm("{ .reg .u64 t; cvta.to.shared.u64 t, %1; cvt.u32.u64 %0, t; }" : "=r"(a) : "l"(p));
    return a;
}

__device__ __forceinline__ void packhl(float x, float y, uint32_t& hi, uint32_t& lo) {
    __nv_bfloat16 hx = __float2bfloat16(x), hy = __float2bfloat16(y);
    __nv_bfloat16 lx = __float2bfloat16(x - __bfloat162float(hx));
    __nv_bfloat16 ly = __float2bfloat16(y - __bfloat162float(hy));
    hi = (uint32_t)__bfloat16_as_ushort(hx) | ((uint32_t)__bfloat16_as_ushort(hy) << 16);
    lo = (uint32_t)__bfloat16_as_ushort(lx) | ((uint32_t)__bfloat16_as_ushort(ly) << 16);
}

// ---------------- split ALL weights: coalesced + high MLP --------------------------
__global__ void __launch_bounds__(256) splitall_kernel(
    const float* __restrict__ wq, const float* __restrict__ wk, const float* __restrict__ wv,
    const float* __restrict__ wo, const float* __restrict__ w1, const float* __restrict__ w2,
    const float* __restrict__ w3,
    __nv_bfloat16* __restrict__ dh, __nv_bfloat16* __restrict__ dl)
{
    const int layer = blockIdx.y;
    const size_t base = (size_t)blockIdx.x * 16384;
    const float* src;
    if (base < 3 * (size_t)M1) {
        const float* t = (base < (size_t)M1) ? wq : (base < 2 * (size_t)M1) ? wk : wv;
        src = t + (size_t)layer * M1 + (base & (M1 - 1));
    } else if (base < 4 * (size_t)M1) {
        src = wo + (size_t)layer * M1 + (base - 3 * (size_t)M1);
    } else if (base < 8 * (size_t)M1) {
        src = w1 + (size_t)layer * 4 * M1 + (base - 4 * (size_t)M1);
    } else if (base < 24 * (size_t)M1) {
        src = w2 + (size_t)layer * 16 * M1 + (base - 8 * (size_t)M1);
    } else {
        src = w3 + (size_t)layer * 4 * M1 + (base - 24 * (size_t)M1);
    }
    const int tid = threadIdx.x;
    float4 v[16];
#pragma unroll
    for (int it = 0; it < 8; ++it) {
        const float* p = src + it * 2048 + tid * 8;
        v[2 * it]     = *(const float4*)p;
        v[2 * it + 1] = *(const float4*)(p + 4);
    }
    __nv_bfloat16* oh = dh + (size_t)layer * WL_ELEMS + base;
    __nv_bfloat16* ol = dl + (size_t)layer * WL_ELEMS + base;
#pragma unroll
    for (int it = 0; it < 8; ++it) {
        const int o = it * 2048 + tid * 8;
        uint2 ph0, pl0, ph1, pl1;
        packhl(v[2*it].x,   v[2*it].y,   ph0.x, pl0.x);
        packhl(v[2*it].z,   v[2*it].w,   ph0.y, pl0.y);
        packhl(v[2*it+1].x, v[2*it+1].y, ph1.x, pl1.x);
        packhl(v[2*it+1].z, v[2*it+1].w, ph1.y, pl1.y);
        *(uint2*)(oh + o)     = ph0;
        *(uint2*)(ol + o)     = pl0;
        *(uint2*)(oh + o + 4) = ph1;
        *(uint2*)(ol + o + 4) = pl1;
    }
}

// ================= bf16 HMMA GEMM: round-8/11 validated config =====================
// KSPLIT: gridDim.z=2, blockIdx.z selects K-half (length K, row stride Kstride);
// writes raw fp32 partial to C + z*2048*N, no bias/relu/res.
#define GSTRIDE 80
#define AH_OFF 0
#define AL_OFF 10240
#define BH_OFF 20480
#define BL_OFF 30720
#define STAGE_SZ 40960
#define GSMEM_TOTAL (2 * STAGE_SZ)

__device__ __forceinline__ void ldm4(uint32_t addr, uint32_t& r0, uint32_t& r1,
                                     uint32_t& r2, uint32_t& r3) {
    asm volatile("ldmatrix.sync.aligned.m8n8.x4.shared.b16 {%0,%1,%2,%3}, [%4];"
                 : "=r"(r0), "=r"(r1), "=r"(r2), "=r"(r3) : "r"(addr));
}
__device__ __forceinline__ void ldm4t(uint32_t addr, uint32_t& r0, uint32_t& r1,
                                      uint32_t& r2, uint32_t& r3) {
    asm volatile("ldmatrix.sync.aligned.m8n8.x4.trans.shared.b16 {%0,%1,%2,%3}, [%4];"
                 : "=r"(r0), "=r"(r1), "=r"(r2), "=r"(r3) : "r"(addr));
}
__device__ __forceinline__ void mma16816(float* c, const uint32_t* a, const uint32_t* b) {
    asm volatile(
        "mma.sync.aligned.m16n8k16.row.col.f32.bf16.bf16.f32 "
        "{%0,%1,%2,%3}, {%4,%5,%6,%7}, {%8,%9}, {%0,%1,%2,%3};"
        : "+f"(c[0]), "+f"(c[1]), "+f"(c[2]), "+f"(c[3])
        : "r"(a[0]), "r"(a[1]), "r"(a[2]), "r"(a[3]), "r"(b[0]), "r"(b[1]));
}
__device__ __forceinline__ void cp16(uint32_t saddr, const void* gaddr) {
    asm volatile("cp.async.cg.shared.global [%0], [%1], 16;" :: "r"(saddr), "l"(gaddr));
}
#define CP_COMMIT() asm volatile("cp.async.commit_group;" ::: "memory")
#define CP_WAIT0()  asm volatile("cp.async.wait_group 0;" ::: "memory")

template<bool BIAS, bool RELU, bool RES, bool OSPLIT, bool KSPLIT>
__global__ void __launch_bounds__(256, 2)
gemm_bf16(int K, int Kstride, int N,
          const __nv_bfloat16* __restrict__ Ah, const __nv_bfloat16* __restrict__ Al,
          const __nv_bfloat16* __restrict__ Bh, const __nv_bfloat16* __restrict__ Bl,
          const float* __restrict__ bias, const float* __restrict__ res,
          float* __restrict__ C,
          __nv_bfloat16* __restrict__ Chi, __nv_bfloat16* __restrict__ Clo)
{
    extern __shared__ __align__(128) char smem[];
    const uint32_t sb = smem_u32(smem);
    const int tid  = threadIdx.x;
    const int wid  = tid >> 5;
    const int lane = tid & 31;
    const int wm   = wid >> 2;
    const int wn   = wid & 3;
    const int m0   = blockIdx.y * 128;
    const int n0   = blockIdx.x * 128;
    const size_t koff = KSPLIT ? (size_t)blockIdx.z * K : 0;

    float acc[4][4][4];
#pragma unroll
    for (int i = 0; i < 4; ++i)
#pragma unroll
        for (int j = 0; j < 4; ++j)
#pragma unroll
            for (int q = 0; q < 4; ++q) acc[i][j][q] = 0.0f;

    const int NC = K >> 5;
    const int lrow = tid >> 1;
    const int lqb  = (tid & 1) * 32;

    const int sub = lane >> 3, r8 = lane & 7;
    const uint32_t a_lane_off = (uint32_t)(((sub & 1) * 8 + r8) * GSTRIDE + ((sub >> 1) * 8) * 2);
    const uint32_t b_lane_off = (uint32_t)((((sub >> 1) * 8) + r8) * GSTRIDE + ((sub & 1) * 8) * 2);

    auto issue = [&](int c) {
        const uint32_t stg  = sb + (uint32_t)(c & 1) * STAGE_SZ;
        const uint32_t soff = (uint32_t)(lrow * GSTRIDE + lqb);
        const size_t   goff = (size_t)lrow * Kstride + (size_t)c * 32 + koff;
        const char* ah = (const char*)(Ah + (size_t)m0 * Kstride + goff) + lqb;
        const char* al = (const char*)(Al + (size_t)m0 * Kstride + goff) + lqb;
        const char* bh = (const char*)(Bh + (size_t)n0 * Kstride + goff) + lqb;
        const char* bl = (const char*)(Bl + (size_t)n0 * Kstride + goff) + lqb;
        cp16(stg + AH_OFF + soff, ah);       cp16(stg + AH_OFF + soff + 16, ah + 16);
        cp16(stg + AL_OFF + soff, al);       cp16(stg + AL_OFF + soff + 16, al + 16);
        cp16(stg + BH_OFF + soff, bh);       cp16(stg + BH_OFF + soff + 16, bh + 16);
        cp16(stg + BL_OFF + soff, bl);       cp16(stg + BL_OFF + soff + 16, bl + 16);
    };

    issue(0); CP_COMMIT();

    for (int c = 0; c < NC; ++c) {
        CP_WAIT0();
        __syncthreads();
        if (c + 1 < NC) { issue(c + 1); CP_COMMIT(); }

        const uint32_t stg  = sb + (uint32_t)(c & 1) * STAGE_SZ;
        const uint32_t ah_b = stg + AH_OFF + (uint32_t)(wm * 64) * GSTRIDE + a_lane_off;
        const uint32_t al_b = stg + AL_OFF + (uint32_t)(wm * 64) * GSTRIDE + a_lane_off;
        const uint32_t bh_b = stg + BH_OFF + (uint32_t)(wn * 32) * GSTRIDE + b_lane_off;
        const uint32_t bl_b = stg + BL_OFF + (uint32_t)(wn * 32) * GSTRIDE + b_lane_off;

#pragma unroll
        for (int ks = 0; ks < 2; ++ks) {
            const uint32_t ko = (uint32_t)(ks * 32);
            uint32_t ahh[4][4], bhh[4][2];
#pragma unroll
            for (int mt = 0; mt < 4; ++mt)
                ldm4(ah_b + (uint32_t)(mt * 16) * GSTRIDE + ko,
                     ahh[mt][0], ahh[mt][1], ahh[mt][2], ahh[mt][3]);
#pragma unroll
            for (int np = 0; np < 2; ++np)
                ldm4(bh_b + (uint32_t)(np * 16) * GSTRIDE + ko,
                     bhh[np*2][0], bhh[np*2][1], bhh[np*2+1][0], bhh[np*2+1][1]);
#pragma unroll
            for (int mt = 0; mt < 4; ++mt)
#pragma unroll
                for (int nt = 0; nt < 4; ++nt)
                    mma16816(acc[mt][nt], ahh[mt], bhh[nt]);
            {
                uint32_t bhl[4][2];
#pragma unroll
                for (int np = 0; np < 2; ++np)
                    ldm4(bl_b + (uint32_t)(np * 16) * GSTRIDE + ko,
                         bhl[np*2][0], bhl[np*2][1], bhl[np*2+1][0], bhl[np*2+1][1]);
#pragma unroll
                for (int mt = 0; mt < 4; ++mt)
#pragma unroll
                    for (int nt = 0; nt < 4; ++nt)
                        mma16816(acc[mt][nt], ahh[mt], bhl[nt]);
            }
            {
                uint32_t ahl[4][4];
#pragma unroll
                for (int mt = 0; mt < 4; ++mt)
                    ldm4(al_b + (uint32_t)(mt * 16) * GSTRIDE + ko,
                         ahl[mt][0], ahl[mt][1], ahl[mt][2], ahl[mt][3]);
#pragma unroll
                for (int mt = 0; mt < 4; ++mt)
#pragma unroll
                    for (int nt = 0; nt < 4; ++nt)
                        mma16816(acc[mt][nt], ahl[mt], bhh[nt]);
            }
        }
        __syncthreads();
    }

    const int erow = m0 + wm * 64 + (lane >> 2);
    const int ecol = n0 + wn * 32 + (lane & 3) * 2;
    float* Cout = KSPLIT ? (C + (size_t)blockIdx.z * 2048 * (size_t)N) : C;
#pragma unroll
    for (int mt = 0; mt < 4; ++mt) {
#pragma unroll
        for (int nt = 0; nt < 4; ++nt) {
            const int r0 = erow + mt * 16;
            const int cc = ecol + nt * 8;
            float2 v0 = make_float2(acc[mt][nt][0], acc[mt][nt][1]);
            float2 v1 = make_float2(acc[mt][nt][2], acc[mt][nt][3]);
            if (!KSPLIT) {
                if (BIAS) {
                    float2 bb = *(const float2*)(bias + cc);
                    v0.x += bb.x; v0.y += bb.y; v1.x += bb.x; v1.y += bb.y;
                }
                if (RELU) {
                    v0.x = fmaxf(v0.x, 0.f); v0.y = fmaxf(v0.y, 0.f);
                    v1.x = fmaxf(v1.x, 0.f); v1.y = fmaxf(v1.y, 0.f);
                }
                if (RES) {
                    float2 r4 = *(const float2*)(res + (size_t)r0 * N + cc);
                    v0.x += r4.x; v0.y += r4.y;
                    float2 r5 = *(const float2*)(res + (size_t)(r0 + 8) * N + cc);
                    v1.x += r5.x; v1.y += r5.y;
                }
            }
            if (OSPLIT) {
                uint32_t h0, l0, h1, l1;
                packhl(v0.x, v0.y, h0, l0);
                packhl(v1.x, v1.y, h1, l1);
                *(uint32_t*)(Chi + (size_t)r0 * N + cc) = h0;
                *(uint32_t*)(Clo + (size_t)r0 * N + cc) = l0;
                *(uint32_t*)(Chi + (size_t)(r0 + 8) * N + cc) = h1;
                *(uint32_t*)(Clo + (size_t)(r0 + 8) * N + cc) = l1;
            } else {
                *(float2*)(Cout + (size_t)r0 * N + cc) = v0;
                *(float2*)(Cout + (size_t)(r0 + 8) * N + cc) = v1;
            }
        }
    }
}

// ---------------- combine K-split partials: px = px + P0 + P1 (+ bias) -------------
template<bool BIAS>
__global__ void __launch_bounds__(256) combine_kernel(float* __restrict__ px,
                                                      const float* __restrict__ P0,
                                                      const float* __restrict__ P1,
                                                      const float* __restrict__ bias)
{
    int i = blockIdx.x * blockDim.x + threadIdx.x;     // float4 index
    float4 a = *(const float4*)(px + (size_t)i * 4);
    float4 p = *(const float4*)(P0 + (size_t)i * 4);
    float4 q = *(const float4*)(P1 + (size_t)i * 4);
    a.x += p.x + q.x; a.y += p.y + q.y; a.z += p.z + q.z; a.w += p.w + q.w;
    if (BIAS) {
        int col = (i * 4) & (DMODEL - 1);
        float4 b = *(const float4*)(bias + col);
        a.x += b.x; a.y += b.y; a.z += b.z; a.w += b.w;
    }
    *(float4*)(px + (size_t)i * 4) = a;
}

// ---------------- conv_in ----------------------------------------------------------
__global__ void conv_in_kernel(const float* __restrict__ x,
                               const float* __restrict__ w,
                               const float* __restrict__ b,
                               float* __restrict__ h)
{
    int idx = blockIdx.x * blockDim.x + threadIdx.x;
    if (idx >= SEQ * DMODEL) return;
    int d = idx & (DMODEL - 1);
    int l = idx >> 10;
    float acc = b[d];
#pragma unroll
    for (int c = 0; c < CIN; ++c) {
#pragma unroll
        for (int t = 0; t < KW; ++t) {
            int lt = l + t - (KW - 1);
            if (lt >= 0) acc += w[(d * CIN + c) * KW + t] * x[c * SEQ + lt];
        }
    }
    h[idx] = fmaxf(acc, 0.0f);
}

// ---------------- conv_out ---------------------------------------------------------
__global__ void conv_out_kernel(const float* __restrict__ xb,
                                const float* __restrict__ w,
                                const float* __restrict__ b,
                                float* __restrict__ out)
{
    int l  = blockIdx.x;
    int co = blockIdx.y;
    float acc = 0.0f;
    for (int d = threadIdx.x; d < DMODEL; d += 128) {
        const float* wp = w + (size_t)(co * DMODEL + d) * KW;
#pragma unroll
        for (int t = 0; t < KW; ++t) {
            int lt = l + t - (KW - 1);
            if (lt >= 0) acc += wp[t] * xb[(size_t)lt * DMODEL + d];
        }
    }
#pragma unroll
    for (int s = 16; s >= 1; s >>= 1) acc += __shfl_xor_sync(0xffffffffu, acc, s);
    __shared__ float red[4];
    if ((threadIdx.x & 31) == 0) red[threadIdx.x >> 5] = acc;
    __syncthreads();
    if (threadIdx.x == 0)
        out[co * SEQ + l] = red[0] + red[1] + red[2] + red[3] + b[co];
}

// ---------------- RMSNorm -> hi/lo split -------------------------------------------
__global__ void __launch_bounds__(256) rmsnorm_split_kernel(const float* __restrict__ x,
                                                            const float* __restrict__ w,
                                                            const float* __restrict__ b,
                                                            __nv_bfloat16* __restrict__ hi,
                                                            __nv_bfloat16* __restrict__ lo)
{
    int l = blockIdx.x;
    const float* xr = x + (size_t)l * DMODEL;
    const int tid = threadIdx.x;
    float4 v = *(const float4*)(xr + tid * 4);
    float ss = v.x * v.x + v.y * v.y + v.z * v.z + v.w * v.w;
#pragma unroll
    for (int s = 16; s >= 1; s >>= 1) ss += __shfl_xor_sync(0xffffffffu, ss, s);
    __shared__ float red[8];
    __shared__ float sinv;
    if ((tid & 31) == 0) red[tid >> 5] = ss;
    __syncthreads();
    if (tid == 0) {
        float t = 0.0f;
#pragma unroll
        for (int i = 0; i < 8; ++i) t += red[i];
        sinv = rsqrtf(t * (1.0f / DMODEL) + 1e-5f);
    }
    __syncthreads();
    float inv = sinv;
    float4 wv = *(const float4*)(w + tid * 4);
    float4 bv = *(const float4*)(b + tid * 4);
    float y0 = v.x * inv * wv.x + bv.x;
    float y1 = v.y * inv * wv.y + bv.y;
    float y2 = v.z * inv * wv.z + bv.z;
    float y3 = v.w * inv * wv.w + bv.w;
    uint2 ph, pl;
    packhl(y0, y1, ph.x, pl.x);
    packhl(y2, y3, ph.y, pl.y);
    *(uint2*)(hi + (size_t)l * DMODEL + tid * 4) = ph;
    *(uint2*)(lo + (size_t)l * DMODEL + tid * 4) = pl;
}

// ---------------- RoPE + split -----------------------------------------------------
__device__ __forceinline__ void split1(float x, __nv_bfloat16* hi, __nv_bfloat16* lo, size_t o) {
    __nv_bfloat16 h = __float2bfloat16(x);
    hi[o] = h;
    lo[o] = __float2bfloat16(x - __bfloat162float(h));
}

__global__ void rope_split_kernel(const float* __restrict__ qkv,
                                  __nv_bfloat16* __restrict__ Qh, __nv_bfloat16* __restrict__ Ql,
                                  __nv_bfloat16* __restrict__ Kh, __nv_bfloat16* __restrict__ Kl,
                                  __nv_bfloat16* __restrict__ Vh, __nv_bfloat16* __restrict__ Vl)
{
    int idx = blockIdx.x * blockDim.x + threadIdx.x;
    if (idx >= SEQ * NHEADS * (HD / 2)) return;
    int j = idx & 31;
    int h = (idx >> 5) & (NHEADS - 1);
    int l = idx >> 9;
    float inv_freq = exp2f(-(float)j * (13.287712379549449f / 32.0f));
    float ang = (float)l * inv_freq;
    float s, c;
    sincosf(ang, &s, &c);
    size_t ib = (size_t)l * QKVS + h * HD + j;
    size_t ob = (size_t)l * DMODEL + h * HD + j;
    float q1 = qkv[ib], q2 = qkv[ib + 32];
    split1((q1 * c - q2 * s) * 0.125f, Qh, Ql, ob);
    split1((q2 * c + q1 * s) * 0.125f, Qh, Ql, ob + 32);
    float k1 = qkv[ib + DMODEL], k2 = qkv[ib + DMODEL + 32];
    split1(k1 * c - k2 * s, Kh, Kl, ob);
    split1(k2 * c + k1 * s, Kh, Kl, ob + 32);
    split1(qkv[ib + 2 * DMODEL], Vh, Vl, ob);
    split1(qkv[ib + 2 * DMODEL + 32], Vh, Vl, ob + 32);
}

// ---------------- MMA flash attention (bf16 3-term, fp32 softmax) ------------------
#define ASTRIDE 144
#define AMM_SMEM (6 * 64 * ASTRIDE)

__global__ void __launch_bounds__(128) attn_mma_kernel(
    const __nv_bfloat16* __restrict__ Qh, const __nv_bfloat16* __restrict__ Ql,
    const __nv_bfloat16* __restrict__ Kh, const __nv_bfloat16* __restrict__ Kl,
    const __nv_bfloat16* __restrict__ Vh, const __nv_bfloat16* __restrict__ Vl,
    __nv_bfloat16* __restrict__ Ohi, __nv_bfloat16* __restrict__ Olo)
{
    extern __shared__ __align__(128) char smem[];
    const uint32_t sb = smem_u32(smem);
    const int h  = blockIdx.y;
    const int qt = blockIdx.x;
    const int q0 = qt * 64;
    const int tid = threadIdx.x, wid = tid >> 5, lane = tid & 31;

    const uint32_t QHo = 0, QLo = 9216, KHo = 18432, KLo = 27648, VHo = 36864, VLo = 46080;

    {
        const int row = tid >> 1, ho = (tid & 1) * 64;
        const uint32_t so = (uint32_t)(row * ASTRIDE + ho);
        const char* gh = (const char*)(Qh + (size_t)(q0 + row) * DMODEL + h * HD) + ho;
        const char* gl = (const char*)(Ql + (size_t)(q0 + row) * DMODEL + h * HD) + ho;
#pragma unroll
        for (int i = 0; i < 4; ++i) {
            cp16(sb + QHo + so + i * 16, gh + i * 16);
            cp16(sb + QLo + so + i * 16, gl + i * 16);
        }
    }
    CP_COMMIT();
    CP_WAIT0();
    __syncthreads();

    const int sub = lane >> 3, r8v = lane & 7;
    const uint32_t a_off = (uint32_t)(((sub & 1) * 8 + r8v) * ASTRIDE + ((sub >> 1) * 8) * 2);
    const uint32_t b_off = (uint32_t)((((sub >> 1) * 8) + r8v) * ASTRIDE + (sub & 1) * 16);
    const uint32_t v_off = (uint32_t)(((sub & 1) * 8 + r8v) * ASTRIDE + (sub >> 1) * 16);

    uint32_t qfh[4][4], qfl[4][4];
#pragma unroll
    for (int ks = 0; ks < 4; ++ks) {
        ldm4(sb + QHo + (uint32_t)(wid * 16) * ASTRIDE + a_off + (uint32_t)(ks * 32),
             qfh[ks][0], qfh[ks][1], qfh[ks][2], qfh[ks][3]);
        ldm4(sb + QLo + (uint32_t)(wid * 16) * ASTRIDE + a_off + (uint32_t)(ks * 32),
             qfl[ks][0], qfl[ks][1], qfl[ks][2], qfl[ks][3]);
    }

    float m0 = -INFINITY, m1 = -INFINITY, l0 = 0.f, l1 = 0.f;
    float oa[8][4];
#pragma unroll
    for (int nt = 0; nt < 8; ++nt)
#pragma unroll
        for (int q = 0; q < 4; ++q) oa[nt][q] = 0.f;

    const int qi0 = q0 + wid * 16 + (lane >> 2);
    const int qi1 = qi0 + 8;

    for (int jt = 0; jt <= qt; ++jt) {
        __syncthreads();
        {
            const int row = tid >> 1, ho = (tid & 1) * 64;
            const uint32_t so = (uint32_t)(row * ASTRIDE + ho);
            const size_t g = (size_t)(jt * 64 + row) * DMODEL + h * HD;
            const char* pkh = (const char*)(Kh + g) + ho;
            const char* pkl = (const char*)(Kl + g) + ho;
            const char* pvh = (const char*)(Vh + g) + ho;
            const char* pvl = (const char*)(Vl + g) + ho;
#pragma unroll
            for (int i = 0; i < 4; ++i) {
                cp16(sb + KHo + so + i * 16, pkh + i * 16);
                cp16(sb + KLo + so + i * 16, pkl + i * 16);
                cp16(sb + VHo + so + i * 16, pvh + i * 16);
                cp16(sb + VLo + so + i * 16, pvl + i * 16);
            }
        }
        CP_COMMIT();
        CP_WAIT0();
        __syncthreads();

        float s[8][4];
#pragma unroll
        for (int nt = 0; nt < 8; ++nt)
#pragma unroll
            for (int q = 0; q < 4; ++q) s[nt][q] = 0.f;

#pragma unroll
        for (int ks = 0; ks < 4; ++ks) {
            const uint32_t ko = (uint32_t)(ks * 32);
            uint32_t kfh[8][2], kfl[8][2];
#pragma unroll
            for (int np = 0; np < 4; ++np) {
                ldm4(sb + KHo + (uint32_t)(np * 16) * ASTRIDE + b_off + ko,
                     kfh[np*2][0], kfh[np*2][1], kfh[np*2+1][0], kfh[np*2+1][1]);
                ldm4(sb + KLo + (uint32_t)(np * 16) * ASTRIDE + b_off + ko,
                     kfl[np*2][0], kfl[np*2][1], kfl[np*2+1][0], kfl[np*2+1][1]);
            }
#pragma unroll
            for (int nt = 0; nt < 8; ++nt) {
                mma16816(s[nt], qfh[ks], kfh[nt]);
                mma16816(s[nt], qfl[ks], kfh[nt]);
                mma16816(s[nt], qfh[ks], kfl[nt]);
            }
        }

        if (jt == qt) {
#pragma unroll
            for (int nt = 0; nt < 8; ++nt) {
                int kjb = jt * 64 + nt * 8 + (lane & 3) * 2;
#pragma unroll
                for (int jj = 0; jj < 2; ++jj) {
                    if (kjb + jj > qi0) s[nt][jj]     = -INFINITY;
                    if (kjb + jj > qi1) s[nt][2 + jj] = -INFINITY;
                }
            }
        }

        float rm0 = -INFINITY, rm1 = -INFINITY;
#pragma unroll
        for (int nt = 0; nt < 8; ++nt) {
            rm0 = fmaxf(rm0, fmaxf(s[nt][0], s[nt][1]));
            rm1 = fmaxf(rm1, fmaxf(s[nt][2], s[nt][3]));
        }
        rm0 = fmaxf(rm0, __shfl_xor_sync(0xffffffffu, rm0, 1));
        rm0 = fmaxf(rm0, __shfl_xor_sync(0xffffffffu, rm0, 2));
        rm1 = fmaxf(rm1, __shfl_xor_sync(0xffffffffu, rm1, 1));
        rm1 = fmaxf(rm1, __shfl_xor_sync(0xffffffffu, rm1, 2));
        float mn0 = fmaxf(m0, rm0), mn1 = fmaxf(m1, rm1);
        float al0 = __expf(m0 - mn0), al1 = __expf(m1 - mn1);
        m0 = mn0; m1 = mn1;
        float rs0 = 0.f, rs1 = 0.f;
#pragma unroll
        for (int nt = 0; nt < 8; ++nt) {
            s[nt][0] = __expf(s[nt][0] - mn0); rs0 += s[nt][0];
            s[nt][1] = __expf(s[nt][1] - mn0); rs0 += s[nt][1];
            s[nt][2] = __expf(s[nt][2] - mn1); rs1 += s[nt][2];
            s[nt][3] = __expf(s[nt][3] - mn1); rs1 += s[nt][3];
        }
        rs0 += __shfl_xor_sync(0xffffffffu, rs0, 1);
        rs0 += __shfl_xor_sync(0xffffffffu, rs0, 2);
        rs1 += __shfl_xor_sync(0xffffffffu, rs1, 1);
        rs1 += __shfl_xor_sync(0xffffffffu, rs1, 2);
        l0 = l0 * al0 + rs0;
        l1 = l1 * al1 + rs1;
#pragma unroll
        for (int nt = 0; nt < 8; ++nt) {
            oa[nt][0] *= al0; oa[nt][1] *= al0;
            oa[nt][2] *= al1; oa[nt][3] *= al1;
        }

#pragma unroll
        for (int ks = 0; ks < 4; ++ks) {
            uint32_t pah[4], pal[4];
            packhl(s[2*ks][0],   s[2*ks][1],   pah[0], pal[0]);
            packhl(s[2*ks][2],   s[2*ks][3],   pah[1], pal[1]);
            packhl(s[2*ks+1][0], s[2*ks+1][1], pah[2], pal[2]);
            packhl(s[2*ks+1][2], s[2*ks+1][3], pah[3], pal[3]);
            uint32_t vfh[8][2], vfl[8][2];
#pragma unroll
            for (int np = 0; np < 4; ++np) {
                ldm4t(sb + VHo + (uint32_t)(ks * 16) * ASTRIDE + v_off + (uint32_t)(np * 32),
                      vfh[np*2][0], vfh[np*2][1], vfh[np*2+1][0], vfh[np*2+1][1]);
                ldm4t(sb + VLo + (uint32_t)(ks * 16) * ASTRIDE + v_off + (uint32_t)(np * 32),
                      vfl[np*2][0], vfl[np*2][1], vfl[np*2+1][0], vfl[np*2+1][1]);
            }
#pragma unroll
            for (int nt = 0; nt < 8; ++nt) {
                mma16816(oa[nt], pah, vfh[nt]);
                mma16816(oa[nt], pal, vfh[nt]);
                mma16816(oa[nt], pah, vfl[nt]);
            }
        }
    }

    float inv0 = 1.f / l0, inv1 = 1.f / l1;
#pragma unroll
    for (int nt = 0; nt < 8; ++nt) {
        int col = h * HD + nt * 8 + (lane & 3) * 2;
        uint32_t hh, ll;
        packhl(oa[nt][0] * inv0, oa[nt][1] * inv0, hh, ll);
        *(uint32_t*)(Ohi + (size_t)qi0 * DMODEL + col) = hh;
        *(uint32_t*)(Olo + (size_t)qi0 * DMODEL + col) = ll;
        packhl(oa[nt][2] * inv1, oa[nt][3] * inv1, hh, ll);
        *(uint32_t*)(Ohi + (size_t)qi1 * DMODEL + col) = hh;
        *(uint32_t*)(Olo + (size_t)qi1 * DMODEL + col) = ll;
    }
}

// ---------------- host launcher ----------------------------------------------------
extern "C" void kernel_launch(void* const* d_in, const int* in_sizes, int n_in,
                              void* d_out, int out_size)
{
    const float* x_in       = (const float*)d_in[0];
    const float* conv_in_w  = (const float*)d_in[1];
    const float* conv_in_b  = (const float*)d_in[2];
    const float* ln1_w      = (const float*)d_in[3];
    const float* ln1_b      = (const float*)d_in[4];
    const float* wq         = (const float*)d_in[5];
    const float* wk         = (const float*)d_in[6];
    const float* wv         = (const float*)d_in[7];
    const float* wo         = (const float*)d_in[8];
    const float* ln2_w      = (const float*)d_in[9];
    const float* ln2_b      = (const float*)d_in[10];
    const float* w1         = (const float*)d_in[11];
    const float* b1         = (const float*)d_in[12];
    const float* w2         = (const float*)d_in[13];
    const float* b2         = (const float*)d_in[14];
    const float* w3         = (const float*)d_in[15];
    const float* b3         = (const float*)d_in[16];
    const float* conv_out_w = (const float*)d_in[17];
    const float* conv_out_b = (const float*)d_in[18];
    float* out = (float*)d_out;

    float *px, *pqkv;
    __nv_bfloat16 *pAh, *pAl, *pAh2, *pAl2, *pWh, *pWl;
    __nv_bfloat16 *pQh, *pQl, *pKh, *pKl, *pVh, *pVl;
    cudaGetSymbolAddress((void**)&px,   g_x);
    cudaGetSymbolAddress((void**)&pqkv, g_qkv);
    cudaGetSymbolAddress((void**)&pAh,  g_Ah);
    cudaGetSymbolAddress((void**)&pAl,  g_Al);
    cudaGetSymbolAddress((void**)&pAh2, g_Ah2);
    cudaGetSymbolAddress((void**)&pAl2, g_Al2);
    cudaGetSymbolAddress((void**)&pWh,  g_WBh);
    cudaGetSymbolAddress((void**)&pWl,  g_WBl);
    cudaGetSymbolAddress((void**)&pQh,  g_Qh);
    cudaGetSymbolAddress((void**)&pQl,  g_Ql);
    cudaGetSymbolAddress((void**)&pKh,  g_Kh);
    cudaGetSymbolAddress((void**)&pKl,  g_Kl);
    cudaGetSymbolAddress((void**)&pVh,  g_Vh);
    cudaGetSymbolAddress((void**)&pVl,  g_Vl);

    cudaFuncSetAttribute(attn_mma_kernel, cudaFuncAttributeMaxDynamicSharedMemorySize, AMM_SMEM);
    cudaFuncSetAttribute(gemm_bf16<false, false, false, false, false>, cudaFuncAttributeMaxDynamicSharedMemorySize, GSMEM_TOTAL);
    cudaFuncSetAttribute(gemm_bf16<true,  true,  false, true,  false>, cudaFuncAttributeMaxDynamicSharedMemorySize, GSMEM_TOTAL);
    cudaFuncSetAttribute(gemm_bf16<false, false, false, false, true >, cudaFuncAttributeMaxDynamicSharedMemorySize, GSMEM_TOTAL);

    conv_in_kernel<<<(SEQ * DMODEL) / 256, 256>>>(x_in, conv_in_w, conv_in_b, px);
    splitall_kernel<<<dim3(WL_ELEMS / 16384, NLAYERS), 256>>>(wq, wk, wv, wo, w1, w2, w3, pWh, pWl);

    const dim3 gQKV(QKVS / 128,   SEQ / 128);
    const dim3 gDz (DMODEL / 128, SEQ / 128, 2);   // K-split grids for wo / w3
    const dim3 gF  (DFF / 128,    SEQ / 128);

    for (int i = 0; i < NLAYERS; ++i) {
        const size_t wl = (size_t)i * WL_ELEMS;
        const __nv_bfloat16* qkvh = pWh + wl;
        const __nv_bfloat16* qkvl = pWl + wl;
        const __nv_bfloat16* woh  = pWh + wl + 3 * (size_t)M1;
        const __nv_bfloat16* wol  = pWl + wl + 3 * (size_t)M1;
        const __nv_bfloat16* w1h  = pWh + wl + 4 * (size_t)M1;
        const __nv_bfloat16* w1l  = pWl + wl + 4 * (size_t)M1;
        const __nv_bfloat16* w2h  = pWh + wl + 8 * (size_t)M1;
        const __nv_bfloat16* w2l  = pWl + wl + 8 * (size_t)M1;
        const __nv_bfloat16* w3h  = pWh + wl + 24 * (size_t)M1;
        const __nv_bfloat16* w3l  = pWl + wl + 24 * (size_t)M1;

        rmsnorm_split_kernel<<<SEQ, 256>>>(px, ln1_w + i * DMODEL, ln1_b + i * DMODEL, pAh, pAl);

        gemm_bf16<false, false, false, false, false><<<gQKV, 256, GSMEM_TOTAL>>>(
            DMODEL, DMODEL, QKVS,
            pAh, pAl, qkvh, qkvl, nullptr, nullptr, pqkv, nullptr, nullptr);

        rope_split_kernel<<<(SEQ * NHEADS * (HD / 2)) / 256, 256>>>(pqkv,
            pQh, pQl, pKh, pKl, pVh, pVl);

        attn_mma_kernel<<<dim3(SEQ / 64, NHEADS), 128, AMM_SMEM>>>(
            pQh, pQl, pKh, pKl, pVh, pVl, pAh, pAl);

        // wo GEMM: K-split x2 (qkv buffer now free -> partials)
        gemm_bf16<false, false, false, false, true><<<gDz, 256, GSMEM_TOTAL>>>(
            DMODEL / 2, DMODEL, DMODEL,
            pAh, pAl, woh, wol, nullptr, nullptr, pqkv, nullptr, nullptr);
        combine_kernel<false><<<(SEQ * DMODEL) / 4 / 256, 256>>>(
            px, pqkv, pqkv + (size_t)SEQ * DMODEL, nullptr);

        rmsnorm_split_kernel<<<SEQ, 256>>>(px, ln2_w + i * DMODEL, ln2_b + i * DMODEL, pAh, pAl);

        gemm_bf16<true, true, false, true, false><<<gF, 256, GSMEM_TOTAL>>>(
            DMODEL, DMODEL, DFF,
            pAh, pAl, w1h, w1l, b1 + (size_t)i * DFF, nullptr, nullptr, pAh2, pAl2);

        gemm_bf16<true, true, false, true, false><<<gF, 256, GSMEM_TOTAL>>>(
            DFF, DFF, DFF,
            pAh2, pAl2, w2h, w2l, b2 + (size_t)i * DFF, nullptr, nullptr, pAh, pAl);

        // w3 GEMM: K-split x2
        gemm_bf16<false, false, false, false, true><<<gDz, 256, GSMEM_TOTAL>>>(
            DFF / 2, DFF, DMODEL,
            pAh, pAl, w3h, w3l, nullptr, nullptr, pqkv, nullptr, nullptr);
        combine_kernel<true><<<(SEQ * DMODEL) / 4 / 256, 256>>>(
            px, pqkv, pqkv + (size_t)SEQ * DMODEL, b3 + (size_t)i * DMODEL);
    }

    conv_out_kernel<<<dim3(SEQ, COUT), 128>>>(px, conv_out_w, conv_out_b, out);
}

// round 16
// speedup vs baseline: 1.2291x; 1.0042x over previous
#include <cuda_runtime.h>
#include <cuda_bf16.h>
#include <math.h>
#include <cstdint>

#define NLAYERS 4
#define NHEADS  16
#define DMODEL  1024
#define DFF     4096
#define KW      7
#define SEQ     2048
#define CIN     4
#define COUT    4
#define HD      64
#define QKVS    3072
#define M1      (1 << 20)
#define WL_ELEMS (28 * M1)

// ---------------- scratch ----------------------------------------------------------
__device__ float g_x  [SEQ*DMODEL];
__device__ float g_qkv[2*SEQ*QKVS];        // K-split partial buffers (QKV and wo/w3)
__device__ __nv_bfloat16 g_Ah [SEQ*DFF];
__device__ __nv_bfloat16 g_Al [SEQ*DFF];
__device__ __nv_bfloat16 g_Ah2[SEQ*DFF];
__device__ __nv_bfloat16 g_Al2[SEQ*DFF];
__device__ __nv_bfloat16 g_WBh[NLAYERS * WL_ELEMS];
__device__ __nv_bfloat16 g_WBl[NLAYERS * WL_ELEMS];
__device__ __nv_bfloat16 g_Qh[SEQ*DMODEL];
__device__ __nv_bfloat16 g_Ql[SEQ*DMODEL];
__device__ __nv_bfloat16 g_Kh[SEQ*DMODEL];
__device__ __nv_bfloat16 g_Kl[SEQ*DMODEL];
__device__ __nv_bfloat16 g_Vh[SEQ*DMODEL];
__device__ __nv_bfloat16 g_Vl[SEQ*DMODEL];

__device__ __forceinline__ uint32_t smem_u32(const void* p) {
    uint32_t a;
    asm("{ .reg .u64 t; cvta.to.shared.u64 t, %1; cvt.u32.u64 %0, t; }" : "=r"(a) : "l"(p));
    return a;
}

__device__ __forceinline__ void packhl(float x, float y, uint32_t& hi, uint32_t& lo) {
    __nv_bfloat16 hx = __float2bfloat16(x), hy = __float2bfloat16(y);
    __nv_bfloat16 lx = __float2bfloat16(x - __bfloat162float(hx));
    __nv_bfloat16 ly = __float2bfloat16(y - __bfloat162float(hy));
    hi = (uint32_t)__bfloat16_as_ushort(hx) | ((uint32_t)__bfloat16_as_ushort(hy) << 16);
    lo = (uint32_t)__bfloat16_as_ushort(lx) | ((uint32_t)__bfloat16_as_ushort(ly) << 16);
}

// ---------------- split ALL weights: coalesced + high MLP --------------------------
__global__ void __launch_bounds__(256) splitall_kernel(
    const float* __restrict__ wq, const float* __restrict__ wk, const float* __restrict__ wv,
    const float* __restrict__ wo, const float* __restrict__ w1, const float* __restrict__ w2,
    const float* __restrict__ w3,
    __nv_bfloat16* __restrict__ dh, __nv_bfloat16* __restrict__ dl)
{
    const int layer = blockIdx.y;
    const size_t base = (size_t)blockIdx.x * 16384;
    const float* src;
    if (base < 3 * (size_t)M1) {
        const float* t = (base < (size_t)M1) ? wq : (base < 2 * (size_t)M1) ? wk : wv;
        src = t + (size_t)layer * M1 + (base & (M1 - 1));
    } else if (base < 4 * (size_t)M1) {
        src = wo + (size_t)layer * M1 + (base - 3 * (size_t)M1);
    } else if (base < 8 * (size_t)M1) {
        src = w1 + (size_t)layer * 4 * M1 + (base - 4 * (size_t)M1);
    } else if (base < 24 * (size_t)M1) {
        src = w2 + (size_t)layer * 16 * M1 + (base - 8 * (size_t)M1);
    } else {
        src = w3 + (size_t)layer * 4 * M1 + (base - 24 * (size_t)M1);
    }
    const int tid = threadIdx.x;
    float4 v[16];
#pragma unroll
    for (int it = 0; it < 8; ++it) {
        const float* p = src + it * 2048 + tid * 8;
        v[2 * it]     = *(const float4*)p;
        v[2 * it + 1] = *(const float4*)(p + 4);
    }
    __nv_bfloat16* oh = dh + (size_t)layer * WL_ELEMS + base;
    __nv_bfloat16* ol = dl + (size_t)layer * WL_ELEMS + base;
#pragma unroll
    for (int it = 0; it < 8; ++it) {
        const int o = it * 2048 + tid * 8;
        uint2 ph0, pl0, ph1, pl1;
        packhl(v[2*it].x,   v[2*it].y,   ph0.x, pl0.x);
        packhl(v[2*it].z,   v[2*it].w,   ph0.y, pl0.y);
        packhl(v[2*it+1].x, v[2*it+1].y, ph1.x, pl1.x);
        packhl(v[2*it+1].z, v[2*it+1].w, ph1.y, pl1.y);
        *(uint2*)(oh + o)     = ph0;
        *(uint2*)(ol + o)     = pl0;
        *(uint2*)(oh + o + 4) = ph1;
        *(uint2*)(ol + o + 4) = pl1;
    }
}

// ================= bf16 HMMA GEMM (locked round-8/11 config; KSPLIT option) ========
#define GSTRIDE 80
#define AH_OFF 0
#define AL_OFF 10240
#define BH_OFF 20480
#define BL_OFF 30720
#define STAGE_SZ 40960
#define GSMEM_TOTAL (2 * STAGE_SZ)

__device__ __forceinline__ void ldm4(uint32_t addr, uint32_t& r0, uint32_t& r1,
                                     uint32_t& r2, uint32_t& r3) {
    asm volatile("ldmatrix.sync.aligned.m8n8.x4.shared.b16 {%0,%1,%2,%3}, [%4];"
                 : "=r"(r0), "=r"(r1), "=r"(r2), "=r"(r3) : "r"(addr));
}
__device__ __forceinline__ void ldm4t(uint32_t addr, uint32_t& r0, uint32_t& r1,
                                      uint32_t& r2, uint32_t& r3) {
    asm volatile("ldmatrix.sync.aligned.m8n8.x4.trans.shared.b16 {%0,%1,%2,%3}, [%4];"
                 : "=r"(r0), "=r"(r1), "=r"(r2), "=r"(r3) : "r"(addr));
}
__device__ __forceinline__ void mma16816(float* c, const uint32_t* a, const uint32_t* b) {
    asm volatile(
        "mma.sync.aligned.m16n8k16.row.col.f32.bf16.bf16.f32 "
        "{%0,%1,%2,%3}, {%4,%5,%6,%7}, {%8,%9}, {%0,%1,%2,%3};"
        : "+f"(c[0]), "+f"(c[1]), "+f"(c[2]), "+f"(c[3])
        : "r"(a[0]), "r"(a[1]), "r"(a[2]), "r"(a[3]), "r"(b[0]), "r"(b[1]));
}
__device__ __forceinline__ void cp16(uint32_t saddr, const void* gaddr) {
    asm volatile("cp.async.cg.shared.global [%0], [%1], 16;" :: "r"(saddr), "l"(gaddr));
}
#define CP_COMMIT() asm volatile("cp.async.commit_group;" ::: "memory")
#define CP_WAIT0()  asm volatile("cp.async.wait_group 0;" ::: "memory")

template<bool BIAS, bool RELU, bool RES, bool OSPLIT, bool KSPLIT>
__global__ void __launch_bounds__(256, 2)
gemm_bf16(int K, int Kstride, int N,
          const __nv_bfloat16* __restrict__ Ah, const __nv_bfloat16* __restrict__ Al,
          const __nv_bfloat16* __restrict__ Bh, const __nv_bfloat16* __restrict__ Bl,
          const float* __restrict__ bias, const float* __restrict__ res,
          float* __restrict__ C,
          __nv_bfloat16* __restrict__ Chi, __nv_bfloat16* __restrict__ Clo)
{
    extern __shared__ __align__(128) char smem[];
    const uint32_t sb = smem_u32(smem);
    const int tid  = threadIdx.x;
    const int wid  = tid >> 5;
    const int lane = tid & 31;
    const int wm   = wid >> 2;
    const int wn   = wid & 3;
    const int m0   = blockIdx.y * 128;
    const int n0   = blockIdx.x * 128;
    const size_t koff = KSPLIT ? (size_t)blockIdx.z * K : 0;

    float acc[4][4][4];
#pragma unroll
    for (int i = 0; i < 4; ++i)
#pragma unroll
        for (int j = 0; j < 4; ++j)
#pragma unroll
            for (int q = 0; q < 4; ++q) acc[i][j][q] = 0.0f;

    const int NC = K >> 5;
    const int lrow = tid >> 1;
    const int lqb  = (tid & 1) * 32;

    const int sub = lane >> 3, r8 = lane & 7;
    const uint32_t a_lane_off = (uint32_t)(((sub & 1) * 8 + r8) * GSTRIDE + ((sub >> 1) * 8) * 2);
    const uint32_t b_lane_off = (uint32_t)((((sub >> 1) * 8) + r8) * GSTRIDE + ((sub & 1) * 8) * 2);

    auto issue = [&](int c) {
        const uint32_t stg  = sb + (uint32_t)(c & 1) * STAGE_SZ;
        const uint32_t soff = (uint32_t)(lrow * GSTRIDE + lqb);
        const size_t   goff = (size_t)lrow * Kstride + (size_t)c * 32 + koff;
        const char* ah = (const char*)(Ah + (size_t)m0 * Kstride + goff) + lqb;
        const char* al = (const char*)(Al + (size_t)m0 * Kstride + goff) + lqb;
        const char* bh = (const char*)(Bh + (size_t)n0 * Kstride + goff) + lqb;
        const char* bl = (const char*)(Bl + (size_t)n0 * Kstride + goff) + lqb;
        cp16(stg + AH_OFF + soff, ah);       cp16(stg + AH_OFF + soff + 16, ah + 16);
        cp16(stg + AL_OFF + soff, al);       cp16(stg + AL_OFF + soff + 16, al + 16);
        cp16(stg + BH_OFF + soff, bh);       cp16(stg + BH_OFF + soff + 16, bh + 16);
        cp16(stg + BL_OFF + soff, bl);       cp16(stg + BL_OFF + soff + 16, bl + 16);
    };

    issue(0); CP_COMMIT();

    for (int c = 0; c < NC; ++c) {
        CP_WAIT0();
        __syncthreads();
        if (c + 1 < NC) { issue(c + 1); CP_COMMIT(); }

        const uint32_t stg  = sb + (uint32_t)(c & 1) * STAGE_SZ;
        const uint32_t ah_b = stg + AH_OFF + (uint32_t)(wm * 64) * GSTRIDE + a_lane_off;
        const uint32_t al_b = stg + AL_OFF + (uint32_t)(wm * 64) * GSTRIDE + a_lane_off;
        const uint32_t bh_b = stg + BH_OFF + (uint32_t)(wn * 32) * GSTRIDE + b_lane_off;
        const uint32_t bl_b = stg + BL_OFF + (uint32_t)(wn * 32) * GSTRIDE + b_lane_off;

#pragma unroll
        for (int ks = 0; ks < 2; ++ks) {
            const uint32_t ko = (uint32_t)(ks * 32);
            uint32_t ahh[4][4], bhh[4][2];
#pragma unroll
            for (int mt = 0; mt < 4; ++mt)
                ldm4(ah_b + (uint32_t)(mt * 16) * GSTRIDE + ko,
                     ahh[mt][0], ahh[mt][1], ahh[mt][2], ahh[mt][3]);
#pragma unroll
            for (int np = 0; np < 2; ++np)
                ldm4(bh_b + (uint32_t)(np * 16) * GSTRIDE + ko,
                     bhh[np*2][0], bhh[np*2][1], bhh[np*2+1][0], bhh[np*2+1][1]);
#pragma unroll
            for (int mt = 0; mt < 4; ++mt)
#pragma unroll
                for (int nt = 0; nt < 4; ++nt)
                    mma16816(acc[mt][nt], ahh[mt], bhh[nt]);
            {
                uint32_t bhl[4][2];
#pragma unroll
                for (int np = 0; np < 2; ++np)
                    ldm4(bl_b + (uint32_t)(np * 16) * GSTRIDE + ko,
                         bhl[np*2][0], bhl[np*2][1], bhl[np*2+1][0], bhl[np*2+1][1]);
#pragma unroll
                for (int mt = 0; mt < 4; ++mt)
#pragma unroll
                    for (int nt = 0; nt < 4; ++nt)
                        mma16816(acc[mt][nt], ahh[mt], bhl[nt]);
            }
            {
                uint32_t ahl[4][4];
#pragma unroll
                for (int mt = 0; mt < 4; ++mt)
                    ldm4(al_b + (uint32_t)(mt * 16) * GSTRIDE + ko,
                         ahl[mt][0], ahl[mt][1], ahl[mt][2], ahl[mt][3]);
#pragma unroll
                for (int mt = 0; mt < 4; ++mt)
#pragma unroll
                    for (int nt = 0; nt < 4; ++nt)
                        mma16816(acc[mt][nt], ahl[mt], bhh[nt]);
            }
        }
        __syncthreads();
    }

    const int erow = m0 + wm * 64 + (lane >> 2);
    const int ecol = n0 + wn * 32 + (lane & 3) * 2;
    float* Cout = KSPLIT ? (C + (size_t)blockIdx.z * 2048 * (size_t)N) : C;
#pragma unroll
    for (int mt = 0; mt < 4; ++mt) {
#pragma unroll
        for (int nt = 0; nt < 4; ++nt) {
            const int r0 = erow + mt * 16;
            const int cc = ecol + nt * 8;
            float2 v0 = make_float2(acc[mt][nt][0], acc[mt][nt][1]);
            float2 v1 = make_float2(acc[mt][nt][2], acc[mt][nt][3]);
            if (!KSPLIT) {
                if (BIAS) {
                    float2 bb = *(const float2*)(bias + cc);
                    v0.x += bb.x; v0.y += bb.y; v1.x += bb.x; v1.y += bb.y;
                }
                if (RELU) {
                    v0.x = fmaxf(v0.x, 0.f); v0.y = fmaxf(v0.y, 0.f);
                    v1.x = fmaxf(v1.x, 0.f); v1.y = fmaxf(v1.y, 0.f);
                }
                if (RES) {
                    float2 r4 = *(const float2*)(res + (size_t)r0 * N + cc);
                    v0.x += r4.x; v0.y += r4.y;
                    float2 r5 = *(const float2*)(res + (size_t)(r0 + 8) * N + cc);
                    v1.x += r5.x; v1.y += r5.y;
                }
            }
            if (OSPLIT) {
                uint32_t h0, l0, h1, l1;
                packhl(v0.x, v0.y, h0, l0);
                packhl(v1.x, v1.y, h1, l1);
                *(uint32_t*)(Chi + (size_t)r0 * N + cc) = h0;
                *(uint32_t*)(Clo + (size_t)r0 * N + cc) = l0;
                *(uint32_t*)(Chi + (size_t)(r0 + 8) * N + cc) = h1;
                *(uint32_t*)(Clo + (size_t)(r0 + 8) * N + cc) = l1;
            } else {
                *(float2*)(Cout + (size_t)r0 * N + cc) = v0;
                *(float2*)(Cout + (size_t)(r0 + 8) * N + cc) = v1;
            }
        }
    }
}

// ---------------- plain combine (last-layer w3): px += P0 + P1 + bias --------------
__global__ void __launch_bounds__(256) combine_kernel(float* __restrict__ px,
                                                      const float* __restrict__ P0,
                                                      const float* __restrict__ P1,
                                                      const float* __restrict__ bias)
{
    int i = blockIdx.x * blockDim.x + threadIdx.x;
    float4 a = *(const float4*)(px + (size_t)i * 4);
    float4 p = *(const float4*)(P0 + (size_t)i * 4);
    float4 q = *(const float4*)(P1 + (size_t)i * 4);
    a.x += p.x + q.x; a.y += p.y + q.y; a.z += p.z + q.z; a.w += p.w + q.w;
    int col = (i * 4) & (DMODEL - 1);
    float4 b = *(const float4*)(bias + col);
    a.x += b.x; a.y += b.y; a.z += b.z; a.w += b.w;
    *(float4*)(px + (size_t)i * 4) = a;
}

// ---------------- fused combine + RMSNorm -> hi/lo split ---------------------------
// one block = one row: a = px + P0 + P1 (+bias); px = a; rmsnorm(a) -> hi/lo
template<bool BIAS>
__global__ void __launch_bounds__(256) combine_rms_kernel(
    float* __restrict__ px, const float* __restrict__ P0, const float* __restrict__ P1,
    const float* __restrict__ bias,
    const float* __restrict__ w, const float* __restrict__ b,
    __nv_bfloat16* __restrict__ hi, __nv_bfloat16* __restrict__ lo)
{
    const int l = blockIdx.x;
    const int tid = threadIdx.x;
    const size_t off = (size_t)l * DMODEL + tid * 4;
    float4 a = *(const float4*)(px + off);
    float4 p = *(const float4*)(P0 + off);
    float4 q = *(const float4*)(P1 + off);
    a.x += p.x + q.x; a.y += p.y + q.y; a.z += p.z + q.z; a.w += p.w + q.w;
    if (BIAS) {
        float4 bb = *(const float4*)(bias + tid * 4);
        a.x += bb.x; a.y += bb.y; a.z += bb.z; a.w += bb.w;
    }
    *(float4*)(px + off) = a;

    float ss = a.x * a.x + a.y * a.y + a.z * a.z + a.w * a.w;
#pragma unroll
    for (int s = 16; s >= 1; s >>= 1) ss += __shfl_xor_sync(0xffffffffu, ss, s);
    __shared__ float red[8];
    __shared__ float sinv;
    if ((tid & 31) == 0) red[tid >> 5] = ss;
    __syncthreads();
    if (tid == 0) {
        float t = 0.0f;
#pragma unroll
        for (int i = 0; i < 8; ++i) t += red[i];
        sinv = rsqrtf(t * (1.0f / DMODEL) + 1e-5f);
    }
    __syncthreads();
    float inv = sinv;
    float4 wv = *(const float4*)(w + tid * 4);
    float4 bv = *(const float4*)(b + tid * 4);
    float y0 = a.x * inv * wv.x + bv.x;
    float y1 = a.y * inv * wv.y + bv.y;
    float y2 = a.z * inv * wv.z + bv.z;
    float y3 = a.w * inv * wv.w + bv.w;
    uint2 ph, pl;
    packhl(y0, y1, ph.x, pl.x);
    packhl(y2, y3, ph.y, pl.y);
    *(uint2*)(hi + off) = ph;
    *(uint2*)(lo + off) = pl;
}

// ---------------- conv_in ----------------------------------------------------------
__global__ void conv_in_kernel(const float* __restrict__ x,
                               const float* __restrict__ w,
                               const float* __restrict__ b,
                               float* __restrict__ h)
{
    int idx = blockIdx.x * blockDim.x + threadIdx.x;
    if (idx >= SEQ * DMODEL) return;
    int d = idx & (DMODEL - 1);
    int l = idx >> 10;
    float acc = b[d];
#pragma unroll
    for (int c = 0; c < CIN; ++c) {
#pragma unroll
        for (int t = 0; t < KW; ++t) {
            int lt = l + t - (KW - 1);
            if (lt >= 0) acc += w[(d * CIN + c) * KW + t] * x[c * SEQ + lt];
        }
    }
    h[idx] = fmaxf(acc, 0.0f);
}

// ---------------- conv_out ---------------------------------------------------------
__global__ void conv_out_kernel(const float* __restrict__ xb,
                                const float* __restrict__ w,
                                const float* __restrict__ b,
                                float* __restrict__ out)
{
    int l  = blockIdx.x;
    int co = blockIdx.y;
    float acc = 0.0f;
    for (int d = threadIdx.x; d < DMODEL; d += 128) {
        const float* wp = w + (size_t)(co * DMODEL + d) * KW;
#pragma unroll
        for (int t = 0; t < KW; ++t) {
            int lt = l + t - (KW - 1);
            if (lt >= 0) acc += wp[t] * xb[(size_t)lt * DMODEL + d];
        }
    }
#pragma unroll
    for (int s = 16; s >= 1; s >>= 1) acc += __shfl_xor_sync(0xffffffffu, acc, s);
    __shared__ float red[4];
    if ((threadIdx.x & 31) == 0) red[threadIdx.x >> 5] = acc;
    __syncthreads();
    if (threadIdx.x == 0)
        out[co * SEQ + l] = red[0] + red[1] + red[2] + red[3] + b[co];
}

// ---------------- RMSNorm -> hi/lo split (standalone, first layer only) ------------
__global__ void __launch_bounds__(256) rmsnorm_split_kernel(const float* __restrict__ x,
                                                            const float* __restrict__ w,
                                                            const float* __restrict__ b,
                                                            __nv_bfloat16* __restrict__ hi,
                                                            __nv_bfloat16* __restrict__ lo)
{
    int l = blockIdx.x;
    const float* xr = x + (size_t)l * DMODEL;
    const int tid = threadIdx.x;
    float4 v = *(const float4*)(xr + tid * 4);
    float ss = v.x * v.x + v.y * v.y + v.z * v.z + v.w * v.w;
#pragma unroll
    for (int s = 16; s >= 1; s >>= 1) ss += __shfl_xor_sync(0xffffffffu, ss, s);
    __shared__ float red[8];
    __shared__ float sinv;
    if ((tid & 31) == 0) red[tid >> 5] = ss;
    __syncthreads();
    if (tid == 0) {
        float t = 0.0f;
#pragma unroll
        for (int i = 0; i < 8; ++i) t += red[i];
        sinv = rsqrtf(t * (1.0f / DMODEL) + 1e-5f);
    }
    __syncthreads();
    float inv = sinv;
    float4 wv = *(const float4*)(w + tid * 4);
    float4 bv = *(const float4*)(b + tid * 4);
    float y0 = v.x * inv * wv.x + bv.x;
    float y1 = v.y * inv * wv.y + bv.y;
    float y2 = v.z * inv * wv.z + bv.z;
    float y3 = v.w * inv * wv.w + bv.w;
    uint2 ph, pl;
    packhl(y0, y1, ph.x, pl.x);
    packhl(y2, y3, ph.y, pl.y);
    *(uint2*)(hi + (size_t)l * DMODEL + tid * 4) = ph;
    *(uint2*)(lo + (size_t)l * DMODEL + tid * 4) = pl;
}

// ---------------- RoPE + split (sums K-split QKV partials) -------------------------
__device__ __forceinline__ void split1(float x, __nv_bfloat16* hi, __nv_bfloat16* lo, size_t o) {
    __nv_bfloat16 h = __float2bfloat16(x);
    hi[o] = h;
    lo[o] = __float2bfloat16(x - __bfloat162float(h));
}

__global__ void rope_split_kernel(const float* __restrict__ qkv,
                                  __nv_bfloat16* __restrict__ Qh, __nv_bfloat16* __restrict__ Ql,
                                  __nv_bfloat16* __restrict__ Kh, __nv_bfloat16* __restrict__ Kl,
                                  __nv_bfloat16* __restrict__ Vh, __nv_bfloat16* __restrict__ Vl)
{
    int idx = blockIdx.x * blockDim.x + threadIdx.x;
    if (idx >= SEQ * NHEADS * (HD / 2)) return;
    int j = idx & 31;
    int h = (idx >> 5) & (NHEADS - 1);
    int l = idx >> 9;
    float inv_freq = exp2f(-(float)j * (13.287712379549449f / 32.0f));
    float ang = (float)l * inv_freq;
    float s, c;
    sincosf(ang, &s, &c);
    const float* P1 = qkv + (size_t)SEQ * QKVS;
    size_t ib = (size_t)l * QKVS + h * HD + j;
    size_t ob = (size_t)l * DMODEL + h * HD + j;
    float q1 = qkv[ib] + P1[ib];
    float q2 = qkv[ib + 32] + P1[ib + 32];
    split1((q1 * c - q2 * s) * 0.125f, Qh, Ql, ob);
    split1((q2 * c + q1 * s) * 0.125f, Qh, Ql, ob + 32);
    float k1 = qkv[ib + DMODEL] + P1[ib + DMODEL];
    float k2 = qkv[ib + DMODEL + 32] + P1[ib + DMODEL + 32];
    split1(k1 * c - k2 * s, Kh, Kl, ob);
    split1(k2 * c + k1 * s, Kh, Kl, ob + 32);
    split1(qkv[ib + 2 * DMODEL] + P1[ib + 2 * DMODEL], Vh, Vl, ob);
    split1(qkv[ib + 2 * DMODEL + 32] + P1[ib + 2 * DMODEL + 32], Vh, Vl, ob + 32);
}

// ---------------- MMA flash attention (bf16 3-term, fp32 softmax) ------------------
#define ASTRIDE 144
#define AMM_SMEM (6 * 64 * ASTRIDE)

__global__ void __launch_bounds__(128) attn_mma_kernel(
    const __nv_bfloat16* __restrict__ Qh, const __nv_bfloat16* __restrict__ Ql,
    const __nv_bfloat16* __restrict__ Kh, const __nv_bfloat16* __restrict__ Kl,
    const __nv_bfloat16* __restrict__ Vh, const __nv_bfloat16* __restrict__ Vl,
    __nv_bfloat16* __restrict__ Ohi, __nv_bfloat16* __restrict__ Olo)
{
    extern __shared__ __align__(128) char smem[];
    const uint32_t sb = smem_u32(smem);
    const int h  = blockIdx.y;
    const int qt = blockIdx.x;
    const int q0 = qt * 64;
    const int tid = threadIdx.x, wid = tid >> 5, lane = tid & 31;

    const uint32_t QHo = 0, QLo = 9216, KHo = 18432, KLo = 27648, VHo = 36864, VLo = 46080;

    {
        const int row = tid >> 1, ho = (tid & 1) * 64;
        const uint32_t so = (uint32_t)(row * ASTRIDE + ho);
        const char* gh = (const char*)(Qh + (size_t)(q0 + row) * DMODEL + h * HD) + ho;
        const char* gl = (const char*)(Ql + (size_t)(q0 + row) * DMODEL + h * HD) + ho;
#pragma unroll
        for (int i = 0; i < 4; ++i) {
            cp16(sb + QHo + so + i * 16, gh + i * 16);
            cp16(sb + QLo + so + i * 16, gl + i * 16);
        }
    }
    CP_COMMIT();
    CP_WAIT0();
    __syncthreads();

    const int sub = lane >> 3, r8v = lane & 7;
    const uint32_t a_off = (uint32_t)(((sub & 1) * 8 + r8v) * ASTRIDE + ((sub >> 1) * 8) * 2);
    const uint32_t b_off = (uint32_t)((((sub >> 1) * 8) + r8v) * ASTRIDE + (sub & 1) * 16);
    const uint32_t v_off = (uint32_t)(((sub & 1) * 8 + r8v) * ASTRIDE + (sub >> 1) * 16);

    uint32_t qfh[4][4], qfl[4][4];
#pragma unroll
    for (int ks = 0; ks < 4; ++ks) {
        ldm4(sb + QHo + (uint32_t)(wid * 16) * ASTRIDE + a_off + (uint32_t)(ks * 32),
             qfh[ks][0], qfh[ks][1], qfh[ks][2], qfh[ks][3]);
        ldm4(sb + QLo + (uint32_t)(wid * 16) * ASTRIDE + a_off + (uint32_t)(ks * 32),
             qfl[ks][0], qfl[ks][1], qfl[ks][2], qfl[ks][3]);
    }

    float m0 = -INFINITY, m1 = -INFINITY, l0 = 0.f, l1 = 0.f;
    float oa[8][4];
#pragma unroll
    for (int nt = 0; nt < 8; ++nt)
#pragma unroll
        for (int q = 0; q < 4; ++q) oa[nt][q] = 0.f;

    const int qi0 = q0 + wid * 16 + (lane >> 2);
    const int qi1 = qi0 + 8;

    for (int jt = 0; jt <= qt; ++jt) {
        __syncthreads();
        {
            const int row = tid >> 1, ho = (tid & 1) * 64;
            const uint32_t so = (uint32_t)(row * ASTRIDE + ho);
            const size_t g = (size_t)(jt * 64 + row) * DMODEL + h * HD;
            const char* pkh = (const char*)(Kh + g) + ho;
            const char* pkl = (const char*)(Kl + g) + ho;
            const char* pvh = (const char*)(Vh + g) + ho;
            const char* pvl = (const char*)(Vl + g) + ho;
#pragma unroll
            for (int i = 0; i < 4; ++i) {
                cp16(sb + KHo + so + i * 16, pkh + i * 16);
                cp16(sb + KLo + so + i * 16, pkl + i * 16);
                cp16(sb + VHo + so + i * 16, pvh + i * 16);
                cp16(sb + VLo + so + i * 16, pvl + i * 16);
            }
        }
        CP_COMMIT();
        CP_WAIT0();
        __syncthreads();

        float s[8][4];
#pragma unroll
        for (int nt = 0; nt < 8; ++nt)
#pragma unroll
            for (int q = 0; q < 4; ++q) s[nt][q] = 0.f;

#pragma unroll
        for (int ks = 0; ks < 4; ++ks) {
            const uint32_t ko = (uint32_t)(ks * 32);
            uint32_t kfh[8][2], kfl[8][2];
#pragma unroll
            for (int np = 0; np < 4; ++np) {
                ldm4(sb + KHo + (uint32_t)(np * 16) * ASTRIDE + b_off + ko,
                     kfh[np*2][0], kfh[np*2][1], kfh[np*2+1][0], kfh[np*2+1][1]);
                ldm4(sb + KLo + (uint32_t)(np * 16) * ASTRIDE + b_off + ko,
                     kfl[np*2][0], kfl[np*2][1], kfl[np*2+1][0], kfl[np*2+1][1]);
            }
#pragma unroll
            for (int nt = 0; nt < 8; ++nt) {
                mma16816(s[nt], qfh[ks], kfh[nt]);
                mma16816(s[nt], qfl[ks], kfh[nt]);
                mma16816(s[nt], qfh[ks], kfl[nt]);
            }
        }

        if (jt == qt) {
#pragma unroll
            for (int nt = 0; nt < 8; ++nt) {
                int kjb = jt * 64 + nt * 8 + (lane & 3) * 2;
#pragma unroll
                for (int jj = 0; jj < 2; ++jj) {
                    if (kjb + jj > qi0) s[nt][jj]     = -INFINITY;
                    if (kjb + jj > qi1) s[nt][2 + jj] = -INFINITY;
                }
            }
        }

        float rm0 = -INFINITY, rm1 = -INFINITY;
#pragma unroll
        for (int nt = 0; nt < 8; ++nt) {
            rm0 = fmaxf(rm0, fmaxf(s[nt][0], s[nt][1]));
            rm1 = fmaxf(rm1, fmaxf(s[nt][2], s[nt][3]));
        }
        rm0 = fmaxf(rm0, __shfl_xor_sync(0xffffffffu, rm0, 1));
        rm0 = fmaxf(rm0, __shfl_xor_sync(0xffffffffu, rm0, 2));
        rm1 = fmaxf(rm1, __shfl_xor_sync(0xffffffffu, rm1, 1));
        rm1 = fmaxf(rm1, __shfl_xor_sync(0xffffffffu, rm1, 2));
        float mn0 = fmaxf(m0, rm0), mn1 = fmaxf(m1, rm1);
        float al0 = __expf(m0 - mn0), al1 = __expf(m1 - mn1);
        m0 = mn0; m1 = mn1;
        float rs0 = 0.f, rs1 = 0.f;
#pragma unroll
        for (int nt = 0; nt < 8; ++nt) {
            s[nt][0] = __expf(s[nt][0] - mn0); rs0 += s[nt][0];
            s[nt][1] = __expf(s[nt][1] - mn0); rs0 += s[nt][1];
            s[nt][2] = __expf(s[nt][2] - mn1); rs1 += s[nt][2];
            s[nt][3] = __expf(s[nt][3] - mn1); rs1 += s[nt][3];
        }
        rs0 += __shfl_xor_sync(0xffffffffu, rs0, 1);
        rs0 += __shfl_xor_sync(0xffffffffu, rs0, 2);
        rs1 += __shfl_xor_sync(0xffffffffu, rs1, 1);
        rs1 += __shfl_xor_sync(0xffffffffu, rs1, 2);
        l0 = l0 * al0 + rs0;
        l1 = l1 * al1 + rs1;
#pragma unroll
        for (int nt = 0; nt < 8; ++nt) {
            oa[nt][0] *= al0; oa[nt][1] *= al0;
            oa[nt][2] *= al1; oa[nt][3] *= al1;
        }

#pragma unroll
        for (int ks = 0; ks < 4; ++ks) {
            uint32_t pah[4], pal[4];
            packhl(s[2*ks][0],   s[2*ks][1],   pah[0], pal[0]);
            packhl(s[2*ks][2],   s[2*ks][3],   pah[1], pal[1]);
            packhl(s[2*ks+1][0], s[2*ks+1][1], pah[2], pal[2]);
            packhl(s[2*ks+1][2], s[2*ks+1][3], pah[3], pal[3]);
            uint32_t vfh[8][2], vfl[8][2];
#pragma unroll
            for (int np = 0; np < 4; ++np) {
                ldm4t(sb + VHo + (uint32_t)(ks * 16) * ASTRIDE + v_off + (uint32_t)(np * 32),
                      vfh[np*2][0], vfh[np*2][1], vfh[np*2+1][0], vfh[np*2+1][1]);
                ldm4t(sb + VLo + (uint32_t)(ks * 16) * ASTRIDE + v_off + (uint32_t)(np * 32),
                      vfl[np*2][0], vfl[np*2][1], vfl[np*2+1][0], vfl[np*2+1][1]);
            }
#pragma unroll
            for (int nt = 0; nt < 8; ++nt) {
                mma16816(oa[nt], pah, vfh[nt]);
                mma16816(oa[nt], pal, vfh[nt]);
                mma16816(oa[nt], pah, vfl[nt]);
            }
        }
    }

    float inv0 = 1.f / l0, inv1 = 1.f / l1;
#pragma unroll
    for (int nt = 0; nt < 8; ++nt) {
        int col = h * HD + nt * 8 + (lane & 3) * 2;
        uint32_t hh, ll;
        packhl(oa[nt][0] * inv0, oa[nt][1] * inv0, hh, ll);
        *(uint32_t*)(Ohi + (size_t)qi0 * DMODEL + col) = hh;
        *(uint32_t*)(Olo + (size_t)qi0 * DMODEL + col) = ll;
        packhl(oa[nt][2] * inv1, oa[nt][3] * inv1, hh, ll);
        *(uint32_t*)(Ohi + (size_t)qi1 * DMODEL + col) = hh;
        *(uint32_t*)(Olo + (size_t)qi1 * DMODEL + col) = ll;
    }
}

// ---------------- host launcher ----------------------------------------------------
extern "C" void kernel_launch(void* const* d_in, const int* in_sizes, int n_in,
                              void* d_out, int out_size)
{
    const float* x_in       = (const float*)d_in[0];
    const float* conv_in_w  = (const float*)d_in[1];
    const float* conv_in_b  = (const float*)d_in[2];
    const float* ln1_w      = (const float*)d_in[3];
    const float* ln1_b      = (const float*)d_in[4];
    const float* wq         = (const float*)d_in[5];
    const float* wk         = (const float*)d_in[6];
    const float* wv         = (const float*)d_in[7];
    const float* wo         = (const float*)d_in[8];
    const float* ln2_w      = (const float*)d_in[9];
    const float* ln2_b      = (const float*)d_in[10];
    const float* w1         = (const float*)d_in[11];
    const float* b1         = (const float*)d_in[12];
    const float* w2         = (const float*)d_in[13];
    const float* b2         = (const float*)d_in[14];
    const float* w3         = (const float*)d_in[15];
    const float* b3         = (const float*)d_in[16];
    const float* conv_out_w = (const float*)d_in[17];
    const float* conv_out_b = (const float*)d_in[18];
    float* out = (float*)d_out;

    float *px, *pqkv;
    __nv_bfloat16 *pAh, *pAl, *pAh2, *pAl2, *pWh, *pWl;
    __nv_bfloat16 *pQh, *pQl, *pKh, *pKl, *pVh, *pVl;
    cudaGetSymbolAddress((void**)&px,   g_x);
    cudaGetSymbolAddress((void**)&pqkv, g_qkv);
    cudaGetSymbolAddress((void**)&pAh,  g_Ah);
    cudaGetSymbolAddress((void**)&pAl,  g_Al);
    cudaGetSymbolAddress((void**)&pAh2, g_Ah2);
    cudaGetSymbolAddress((void**)&pAl2, g_Al2);
    cudaGetSymbolAddress((void**)&pWh,  g_WBh);
    cudaGetSymbolAddress((void**)&pWl,  g_WBl);
    cudaGetSymbolAddress((void**)&pQh,  g_Qh);
    cudaGetSymbolAddress((void**)&pQl,  g_Ql);
    cudaGetSymbolAddress((void**)&pKh,  g_Kh);
    cudaGetSymbolAddress((void**)&pKl,  g_Kl);
    cudaGetSymbolAddress((void**)&pVh,  g_Vh);
    cudaGetSymbolAddress((void**)&pVl,  g_Vl);

    cudaFuncSetAttribute(attn_mma_kernel, cudaFuncAttributeMaxDynamicSharedMemorySize, AMM_SMEM);
    cudaFuncSetAttribute(gemm_bf16<true,  true,  false, true,  false>, cudaFuncAttributeMaxDynamicSharedMemorySize, GSMEM_TOTAL);
    cudaFuncSetAttribute(gemm_bf16<false, false, false, false, true >, cudaFuncAttributeMaxDynamicSharedMemorySize, GSMEM_TOTAL);

    conv_in_kernel<<<(SEQ * DMODEL) / 256, 256>>>(x_in, conv_in_w, conv_in_b, px);
    splitall_kernel<<<dim3(WL_ELEMS / 16384, NLAYERS), 256>>>(wq, wk, wv, wo, w1, w2, w3, pWh, pWl);
    rmsnorm_split_kernel<<<SEQ, 256>>>(px, ln1_w, ln1_b, pAh, pAl);

    const dim3 gQKVz(QKVS / 128,   SEQ / 128, 2);
    const dim3 gDz  (DMODEL / 128, SEQ / 128, 2);
    const dim3 gF   (DFF / 128,    SEQ / 128);

    for (int i = 0; i < NLAYERS; ++i) {
        const size_t wl = (size_t)i * WL_ELEMS;
        const __nv_bfloat16* qkvh = pWh + wl;
        const __nv_bfloat16* qkvl = pWl + wl;
        const __nv_bfloat16* woh  = pWh + wl + 3 * (size_t)M1;
        const __nv_bfloat16* wol  = pWl + wl + 3 * (size_t)M1;
        const __nv_bfloat16* w1h  = pWh + wl + 4 * (size_t)M1;
        const __nv_bfloat16* w1l  = pWl + wl + 4 * (size_t)M1;
        const __nv_bfloat16* w2h  = pWh + wl + 8 * (size_t)M1;
        const __nv_bfloat16* w2l  = pWl + wl + 8 * (size_t)M1;
        const __nv_bfloat16* w3h  = pWh + wl + 24 * (size_t)M1;
        const __nv_bfloat16* w3l  = pWl + wl + 24 * (size_t)M1;

        // QKV: K-split x2; partials at pqkv and pqkv + SEQ*QKVS (rope_split sums)
        gemm_bf16<false, false, false, false, true><<<gQKVz, 256, GSMEM_TOTAL>>>(
            DMODEL / 2, DMODEL, QKVS,
            pAh, pAl, qkvh, qkvl, nullptr, nullptr, pqkv, nullptr, nullptr);

        rope_split_kernel<<<(SEQ * NHEADS * (HD / 2)) / 256, 256>>>(pqkv,
            pQh, pQl, pKh, pKl, pVh, pVl);

        attn_mma_kernel<<<dim3(SEQ / 64, NHEADS), 128, AMM_SMEM>>>(
            pQh, pQl, pKh, pKl, pVh, pVl, pAh, pAl);

        // wo: K-split x2 -> fused combine + rmsnorm(ln2)
        gemm_bf16<false, false, false, false, true><<<gDz, 256, GSMEM_TOTAL>>>(
            DMODEL / 2, DMODEL, DMODEL,
            pAh, pAl, woh, wol, nullptr, nullptr, pqkv, nullptr, nullptr);
        combine_rms_kernel<false><<<SEQ, 256>>>(px, pqkv, pqkv + (size_t)SEQ * DMODEL,
            nullptr, ln2_w + i * DMODEL, ln2_b + i * DMODEL, pAh, pAl);

        gemm_bf16<true, true, false, true, false><<<gF, 256, GSMEM_TOTAL>>>(
            DMODEL, DMODEL, DFF,
            pAh, pAl, w1h, w1l, b1 + (size_t)i * DFF, nullptr, nullptr, pAh2, pAl2);

        gemm_bf16<true, true, false, true, false><<<gF, 256, GSMEM_TOTAL>>>(
            DFF, DFF, DFF,
            pAh2, pAl2, w2h, w2l, b2 + (size_t)i * DFF, nullptr, nullptr, pAh, pAl);

        // w3: K-split x2 -> fused combine(+b3) + rmsnorm(ln1 of next layer)
        gemm_bf16<false, false, false, false, true><<<gDz, 256, GSMEM_TOTAL>>>(
            DFF / 2, DFF, DMODEL,
            pAh, pAl, w3h, w3l, nullptr, nullptr, pqkv, nullptr, nullptr);
        if (i + 1 < NLAYERS) {
            combine_rms_kernel<true><<<SEQ, 256>>>(px, pqkv, pqkv + (size_t)SEQ * DMODEL,
                b3 + (size_t)i * DMODEL,
                ln1_w + (i + 1) * DMODEL, ln1_b + (i + 1) * DMODEL, pAh, pAl);
        } else {
            combine_kernel<<<(SEQ * DMODEL) / 4 / 256, 256>>>(
                px, pqkv, pqkv + (size_t)SEQ * DMODEL, b3 + (size_t)i * DMODEL);
        }
    }

    conv_out_kernel<<<dim3(SEQ, COUT), 128>>>(px, conv_out_w, conv_out_b, out);
}

// round 17
// speedup vs baseline: 1.2391x; 1.0081x over previous
#include <cuda_runtime.h>
#include <cuda_bf16.h>
#include <math.h>
#include <cstdint>

#define NLAYERS 4
#define NHEADS  16
#define DMODEL  1024
#define DFF     4096
#define KW      7
#define SEQ     2048
#define CIN     4
#define COUT    4
#define HD      64
#define QKVS    3072
#define M1      (1 << 20)
#define WL_ELEMS (28 * M1)

// ---------------- scratch ----------------------------------------------------------
__device__ float g_x  [SEQ*DMODEL];
__device__ float g_qkv[2*SEQ*QKVS];        // QKV out / attn partials / wo,w3 partials
__device__ float g_ml [2*NHEADS*SEQ*2];    // attention (m, l) partials
__device__ __nv_bfloat16 g_Ah [SEQ*DFF];
__device__ __nv_bfloat16 g_Al [SEQ*DFF];
__device__ __nv_bfloat16 g_Ah2[SEQ*DFF];
__device__ __nv_bfloat16 g_Al2[SEQ*DFF];
__device__ __nv_bfloat16 g_WBh[NLAYERS * WL_ELEMS];
__device__ __nv_bfloat16 g_WBl[NLAYERS * WL_ELEMS];
__device__ __nv_bfloat16 g_Qh[SEQ*DMODEL];
__device__ __nv_bfloat16 g_Ql[SEQ*DMODEL];
__device__ __nv_bfloat16 g_Kh[SEQ*DMODEL];
__device__ __nv_bfloat16 g_Kl[SEQ*DMODEL];
__device__ __nv_bfloat16 g_Vh[SEQ*DMODEL];
__device__ __nv_bfloat16 g_Vl[SEQ*DMODEL];

__device__ __forceinline__ uint32_t smem_u32(const void* p) {
    uint32_t a;
    asm("{ .reg .u64 t; cvta.to.shared.u64 t, %1; cvt.u32.u64 %0, t; }" : "=r"(a) : "l"(p));
    return a;
}

__device__ __forceinline__ void packhl(float x, float y, uint32_t& hi, uint32_t& lo) {
    __nv_bfloat16 hx = __float2bfloat16(x), hy = __float2bfloat16(y);
    __nv_bfloat16 lx = __float2bfloat16(x - __bfloat162float(hx));
    __nv_bfloat16 ly = __float2bfloat16(y - __bfloat162float(hy));
    hi = (uint32_t)__bfloat16_as_ushort(hx) | ((uint32_t)__bfloat16_as_ushort(hy) << 16);
    lo = (uint32_t)__bfloat16_as_ushort(lx) | ((uint32_t)__bfloat16_as_ushort(ly) << 16);
}

// ---------------- split ALL weights ------------------------------------------------
__global__ void __launch_bounds__(256) splitall_kernel(
    const float* __restrict__ wq, const float* __restrict__ wk, const float* __restrict__ wv,
    const float* __restrict__ wo, const float* __restrict__ w1, const float* __restrict__ w2,
    const float* __restrict__ w3,
    __nv_bfloat16* __restrict__ dh, __nv_bfloat16* __restrict__ dl)
{
    const int layer = blockIdx.y;
    const size_t base = (size_t)blockIdx.x * 16384;
    const float* src;
    if (base < 3 * (size_t)M1) {
        const float* t = (base < (size_t)M1) ? wq : (base < 2 * (size_t)M1) ? wk : wv;
        src = t + (size_t)layer * M1 + (base & (M1 - 1));
    } else if (base < 4 * (size_t)M1) {
        src = wo + (size_t)layer * M1 + (base - 3 * (size_t)M1);
    } else if (base < 8 * (size_t)M1) {
        src = w1 + (size_t)layer * 4 * M1 + (base - 4 * (size_t)M1);
    } else if (base < 24 * (size_t)M1) {
        src = w2 + (size_t)layer * 16 * M1 + (base - 8 * (size_t)M1);
    } else {
        src = w3 + (size_t)layer * 4 * M1 + (base - 24 * (size_t)M1);
    }
    const int tid = threadIdx.x;
    float4 v[16];
#pragma unroll
    for (int it = 0; it < 8; ++it) {
        const float* p = src + it * 2048 + tid * 8;
        v[2 * it]     = *(const float4*)p;
        v[2 * it + 1] = *(const float4*)(p + 4);
    }
    __nv_bfloat16* oh = dh + (size_t)layer * WL_ELEMS + base;
    __nv_bfloat16* ol = dl + (size_t)layer * WL_ELEMS + base;
#pragma unroll
    for (int it = 0; it < 8; ++it) {
        const int o = it * 2048 + tid * 8;
        uint2 ph0, pl0, ph1, pl1;
        packhl(v[2*it].x,   v[2*it].y,   ph0.x, pl0.x);
        packhl(v[2*it].z,   v[2*it].w,   ph0.y, pl0.y);
        packhl(v[2*it+1].x, v[2*it+1].y, ph1.x, pl1.x);
        packhl(v[2*it+1].z, v[2*it+1].w, ph1.y, pl1.y);
        *(uint2*)(oh + o)     = ph0;
        *(uint2*)(ol + o)     = pl0;
        *(uint2*)(oh + o + 4) = ph1;
        *(uint2*)(ol + o + 4) = pl1;
    }
}

// ================= bf16 HMMA GEMM (locked config; KSPLIT option) ===================
#define GSTRIDE 80
#define AH_OFF 0
#define AL_OFF 10240
#define BH_OFF 20480
#define BL_OFF 30720
#define STAGE_SZ 40960
#define GSMEM_TOTAL (2 * STAGE_SZ)

__device__ __forceinline__ void ldm4(uint32_t addr, uint32_t& r0, uint32_t& r1,
                                     uint32_t& r2, uint32_t& r3) {
    asm volatile("ldmatrix.sync.aligned.m8n8.x4.shared.b16 {%0,%1,%2,%3}, [%4];"
                 : "=r"(r0), "=r"(r1), "=r"(r2), "=r"(r3) : "r"(addr));
}
__device__ __forceinline__ void ldm4t(uint32_t addr, uint32_t& r0, uint32_t& r1,
                                      uint32_t& r2, uint32_t& r3) {
    asm volatile("ldmatrix.sync.aligned.m8n8.x4.trans.shared.b16 {%0,%1,%2,%3}, [%4];"
                 : "=r"(r0), "=r"(r1), "=r"(r2), "=r"(r3) : "r"(addr));
}
__device__ __forceinline__ void mma16816(float* c, const uint32_t* a, const uint32_t* b) {
    asm volatile(
        "mma.sync.aligned.m16n8k16.row.col.f32.bf16.bf16.f32 "
        "{%0,%1,%2,%3}, {%4,%5,%6,%7}, {%8,%9}, {%0,%1,%2,%3};"
        : "+f"(c[0]), "+f"(c[1]), "+f"(c[2]), "+f"(c[3])
        : "r"(a[0]), "r"(a[1]), "r"(a[2]), "r"(a[3]), "r"(b[0]), "r"(b[1]));
}
__device__ __forceinline__ void cp16(uint32_t saddr, const void* gaddr) {
    asm volatile("cp.async.cg.shared.global [%0], [%1], 16;" :: "r"(saddr), "l"(gaddr));
}
#define CP_COMMIT() asm volatile("cp.async.commit_group;" ::: "memory")
#define CP_WAIT0()  asm volatile("cp.async.wait_group 0;" ::: "memory")

template<bool BIAS, bool RELU, bool RES, bool OSPLIT, bool KSPLIT>
__global__ void __launch_bounds__(256, 2)
gemm_bf16(int K, int Kstride, int N,
          const __nv_bfloat16* __restrict__ Ah, const __nv_bfloat16* __restrict__ Al,
          const __nv_bfloat16* __restrict__ Bh, const __nv_bfloat16* __restrict__ Bl,
          const float* __restrict__ bias, const float* __restrict__ res,
          float* __restrict__ C,
          __nv_bfloat16* __restrict__ Chi, __nv_bfloat16* __restrict__ Clo)
{
    extern __shared__ __align__(128) char smem[];
    const uint32_t sb = smem_u32(smem);
    const int tid  = threadIdx.x;
    const int wid  = tid >> 5;
    const int lane = tid & 31;
    const int wm   = wid >> 2;
    const int wn   = wid & 3;
    const int m0   = blockIdx.y * 128;
    const int n0   = blockIdx.x * 128;
    const size_t koff = KSPLIT ? (size_t)blockIdx.z * K : 0;

    float acc[4][4][4];
#pragma unroll
    for (int i = 0; i < 4; ++i)
#pragma unroll
        for (int j = 0; j < 4; ++j)
#pragma unroll
            for (int q = 0; q < 4; ++q) acc[i][j][q] = 0.0f;

    const int NC = K >> 5;
    const int lrow = tid >> 1;
    const int lqb  = (tid & 1) * 32;

    const int sub = lane >> 3, r8 = lane & 7;
    const uint32_t a_lane_off = (uint32_t)(((sub & 1) * 8 + r8) * GSTRIDE + ((sub >> 1) * 8) * 2);
    const uint32_t b_lane_off = (uint32_t)((((sub >> 1) * 8) + r8) * GSTRIDE + ((sub & 1) * 8) * 2);

    auto issue = [&](int c) {
        const uint32_t stg  = sb + (uint32_t)(c & 1) * STAGE_SZ;
        const uint32_t soff = (uint32_t)(lrow * GSTRIDE + lqb);
        const size_t   goff = (size_t)lrow * Kstride + (size_t)c * 32 + koff;
        const char* ah = (const char*)(Ah + (size_t)m0 * Kstride + goff) + lqb;
        const char* al = (const char*)(Al + (size_t)m0 * Kstride + goff) + lqb;
        const char* bh = (const char*)(Bh + (size_t)n0 * Kstride + goff) + lqb;
        const char* bl = (const char*)(Bl + (size_t)n0 * Kstride + goff) + lqb;
        cp16(stg + AH_OFF + soff, ah);       cp16(stg + AH_OFF + soff + 16, ah + 16);
        cp16(stg + AL_OFF + soff, al);       cp16(stg + AL_OFF + soff + 16, al + 16);
        cp16(stg + BH_OFF + soff, bh);       cp16(stg + BH_OFF + soff + 16, bh + 16);
        cp16(stg + BL_OFF + soff, bl);       cp16(stg + BL_OFF + soff + 16, bl + 16);
    };

    issue(0); CP_COMMIT();

    for (int c = 0; c < NC; ++c) {
        CP_WAIT0();
        __syncthreads();
        if (c + 1 < NC) { issue(c + 1); CP_COMMIT(); }

        const uint32_t stg  = sb + (uint32_t)(c & 1) * STAGE_SZ;
        const uint32_t ah_b = stg + AH_OFF + (uint32_t)(wm * 64) * GSTRIDE + a_lane_off;
        const uint32_t al_b = stg + AL_OFF + (uint32_t)(wm * 64) * GSTRIDE + a_lane_off;
        const uint32_t bh_b = stg + BH_OFF + (uint32_t)(wn * 32) * GSTRIDE + b_lane_off;
        const uint32_t bl_b = stg + BL_OFF + (uint32_t)(wn * 32) * GSTRIDE + b_lane_off;

#pragma unroll
        for (int ks = 0; ks < 2; ++ks) {
            const uint32_t ko = (uint32_t)(ks * 32);
            uint32_t ahh[4][4], bhh[4][2];
#pragma unroll
            for (int mt = 0; mt < 4; ++mt)
                ldm4(ah_b + (uint32_t)(mt * 16) * GSTRIDE + ko,
                     ahh[mt][0], ahh[mt][1], ahh[mt][2], ahh[mt][3]);
#pragma unroll
            for (int np = 0; np < 2; ++np)
                ldm4(bh_b + (uint32_t)(np * 16) * GSTRIDE + ko,
                     bhh[np*2][0], bhh[np*2][1], bhh[np*2+1][0], bhh[np*2+1][1]);
#pragma unroll
            for (int mt = 0; mt < 4; ++mt)
#pragma unroll
                for (int nt = 0; nt < 4; ++nt)
                    mma16816(acc[mt][nt], ahh[mt], bhh[nt]);
            {
                uint32_t bhl[4][2];
#pragma unroll
                for (int np = 0; np < 2; ++np)
                    ldm4(bl_b + (uint32_t)(np * 16) * GSTRIDE + ko,
                         bhl[np*2][0], bhl[np*2][1], bhl[np*2+1][0], bhl[np*2+1][1]);
#pragma unroll
                for (int mt = 0; mt < 4; ++mt)
#pragma unroll
                    for (int nt = 0; nt < 4; ++nt)
                        mma16816(acc[mt][nt], ahh[mt], bhl[nt]);
            }
            {
                uint32_t ahl[4][4];
#pragma unroll
                for (int mt = 0; mt < 4; ++mt)
                    ldm4(al_b + (uint32_t)(mt * 16) * GSTRIDE + ko,
                         ahl[mt][0], ahl[mt][1], ahl[mt][2], ahl[mt][3]);
#pragma unroll
                for (int mt = 0; mt < 4; ++mt)
#pragma unroll
                    for (int nt = 0; nt < 4; ++nt)
                        mma16816(acc[mt][nt], ahl[mt], bhh[nt]);
            }
        }
        __syncthreads();
    }

    const int erow = m0 + wm * 64 + (lane >> 2);
    const int ecol = n0 + wn * 32 + (lane & 3) * 2;
    float* Cout = KSPLIT ? (C + (size_t)blockIdx.z * 2048 * (size_t)N) : C;
#pragma unroll
    for (int mt = 0; mt < 4; ++mt) {
#pragma unroll
        for (int nt = 0; nt < 4; ++nt) {
            const int r0 = erow + mt * 16;
            const int cc = ecol + nt * 8;
            float2 v0 = make_float2(acc[mt][nt][0], acc[mt][nt][1]);
            float2 v1 = make_float2(acc[mt][nt][2], acc[mt][nt][3]);
            if (!KSPLIT) {
                if (BIAS) {
                    float2 bb = *(const float2*)(bias + cc);
                    v0.x += bb.x; v0.y += bb.y; v1.x += bb.x; v1.y += bb.y;
                }
                if (RELU) {
                    v0.x = fmaxf(v0.x, 0.f); v0.y = fmaxf(v0.y, 0.f);
                    v1.x = fmaxf(v1.x, 0.f); v1.y = fmaxf(v1.y, 0.f);
                }
                if (RES) {
                    float2 r4 = *(const float2*)(res + (size_t)r0 * N + cc);
                    v0.x += r4.x; v0.y += r4.y;
                    float2 r5 = *(const float2*)(res + (size_t)(r0 + 8) * N + cc);
                    v1.x += r5.x; v1.y += r5.y;
                }
            }
            if (OSPLIT) {
                uint32_t h0, l0, h1, l1;
                packhl(v0.x, v0.y, h0, l0);
                packhl(v1.x, v1.y, h1, l1);
                *(uint32_t*)(Chi + (size_t)r0 * N + cc) = h0;
                *(uint32_t*)(Clo + (size_t)r0 * N + cc) = l0;
                *(uint32_t*)(Chi + (size_t)(r0 + 8) * N + cc) = h1;
                *(uint32_t*)(Clo + (size_t)(r0 + 8) * N + cc) = l1;
            } else {
                *(float2*)(Cout + (size_t)r0 * N + cc) = v0;
                *(float2*)(Cout + (size_t)(r0 + 8) * N + cc) = v1;
            }
        }
    }
}

// ---------------- plain combine (last-layer w3) ------------------------------------
__global__ void __launch_bounds__(256) combine_kernel(float* __restrict__ px,
                                                      const float* __restrict__ P0,
                                                      const float* __restrict__ P1,
                                                      const float* __restrict__ bias)
{
    int i = blockIdx.x * blockDim.x + threadIdx.x;
    float4 a = *(const float4*)(px + (size_t)i * 4);
    float4 p = *(const float4*)(P0 + (size_t)i * 4);
    float4 q = *(const float4*)(P1 + (size_t)i * 4);
    a.x += p.x + q.x; a.y += p.y + q.y; a.z += p.z + q.z; a.w += p.w + q.w;
    int col = (i * 4) & (DMODEL - 1);
    float4 b = *(const float4*)(bias + col);
    a.x += b.x; a.y += b.y; a.z += b.z; a.w += b.w;
    *(float4*)(px + (size_t)i * 4) = a;
}

// ---------------- fused combine + RMSNorm -> hi/lo split ---------------------------
template<bool BIAS>
__global__ void __launch_bounds__(256) combine_rms_kernel(
    float* __restrict__ px, const float* __restrict__ P0, const float* __restrict__ P1,
    const float* __restrict__ bias,
    const float* __restrict__ w, const float* __restrict__ b,
    __nv_bfloat16* __restrict__ hi, __nv_bfloat16* __restrict__ lo)
{
    const int l = blockIdx.x;
    const int tid = threadIdx.x;
    const size_t off = (size_t)l * DMODEL + tid * 4;
    float4 a = *(const float4*)(px + off);
    float4 p = *(const float4*)(P0 + off);
    float4 q = *(const float4*)(P1 + off);
    a.x += p.x + q.x; a.y += p.y + q.y; a.z += p.z + q.z; a.w += p.w + q.w;
    if (BIAS) {
        float4 bb = *(const float4*)(bias + tid * 4);
        a.x += bb.x; a.y += bb.y; a.z += bb.z; a.w += bb.w;
    }
    *(float4*)(px + off) = a;

    float ss = a.x * a.x + a.y * a.y + a.z * a.z + a.w * a.w;
#pragma unroll
    for (int s = 16; s >= 1; s >>= 1) ss += __shfl_xor_sync(0xffffffffu, ss, s);
    __shared__ float red[8];
    __shared__ float sinv;
    if ((tid & 31) == 0) red[tid >> 5] = ss;
    __syncthreads();
    if (tid == 0) {
        float t = 0.0f;
#pragma unroll
        for (int i = 0; i < 8; ++i) t += red[i];
        sinv = rsqrtf(t * (1.0f / DMODEL) + 1e-5f);
    }
    __syncthreads();
    float inv = sinv;
    float4 wv = *(const float4*)(w + tid * 4);
    float4 bv = *(const float4*)(b + tid * 4);
    float y0 = a.x * inv * wv.x + bv.x;
    float y1 = a.y * inv * wv.y + bv.y;
    float y2 = a.z * inv * wv.z + bv.z;
    float y3 = a.w * inv * wv.w + bv.w;
    uint2 ph, pl;
    packhl(y0, y1, ph.x, pl.x);
    packhl(y2, y3, ph.y, pl.y);
    *(uint2*)(hi + off) = ph;
    *(uint2*)(lo + off) = pl;
}

// ---------------- conv_in ----------------------------------------------------------
__global__ void conv_in_kernel(const float* __restrict__ x,
                               const float* __restrict__ w,
                               const float* __restrict__ b,
                               float* __restrict__ h)
{
    int idx = blockIdx.x * blockDim.x + threadIdx.x;
    if (idx >= SEQ * DMODEL) return;
    int d = idx & (DMODEL - 1);
    int l = idx >> 10;
    float acc = b[d];
#pragma unroll
    for (int c = 0; c < CIN; ++c) {
#pragma unroll
        for (int t = 0; t < KW; ++t) {
            int lt = l + t - (KW - 1);
            if (lt >= 0) acc += w[(d * CIN + c) * KW + t] * x[c * SEQ + lt];
        }
    }
    h[idx] = fmaxf(acc, 0.0f);
}

// ---------------- conv_out ---------------------------------------------------------
__global__ void conv_out_kernel(const float* __restrict__ xb,
                                const float* __restrict__ w,
                                const float* __restrict__ b,
                                float* __restrict__ out)
{
    int l  = blockIdx.x;
    int co = blockIdx.y;
    float acc = 0.0f;
    for (int d = threadIdx.x; d < DMODEL; d += 128) {
        const float* wp = w + (size_t)(co * DMODEL + d) * KW;
#pragma unroll
        for (int t = 0; t < KW; ++t) {
            int lt = l + t - (KW - 1);
            if (lt >= 0) acc += wp[t] * xb[(size_t)lt * DMODEL + d];
        }
    }
#pragma unroll
    for (int s = 16; s >= 1; s >>= 1) acc += __shfl_xor_sync(0xffffffffu, acc, s);
    __shared__ float red[4];
    if ((threadIdx.x & 31) == 0) red[threadIdx.x >> 5] = acc;
    __syncthreads();
    if (threadIdx.x == 0)
        out[co * SEQ + l] = red[0] + red[1] + red[2] + red[3] + b[co];
}

// ---------------- RMSNorm -> hi/lo split (layer 0) ----------------------------------
__global__ void __launch_bounds__(256) rmsnorm_split_kernel(const float* __restrict__ x,
                                                            const float* __restrict__ w,
                                                            const float* __restrict__ b,
                                                            __nv_bfloat16* __restrict__ hi,
                                                            __nv_bfloat16* __restrict__ lo)
{
    int l = blockIdx.x;
    const float* xr = x + (size_t)l * DMODEL;
    const int tid = threadIdx.x;
    float4 v = *(const float4*)(xr + tid * 4);
    float ss = v.x * v.x + v.y * v.y + v.z * v.z + v.w * v.w;
#pragma unroll
    for (int s = 16; s >= 1; s >>= 1) ss += __shfl_xor_sync(0xffffffffu, ss, s);
    __shared__ float red[8];
    __shared__ float sinv;
    if ((tid & 31) == 0) red[tid >> 5] = ss;
    __syncthreads();
    if (tid == 0) {
        float t = 0.0f;
#pragma unroll
        for (int i = 0; i < 8; ++i) t += red[i];
        sinv = rsqrtf(t * (1.0f / DMODEL) + 1e-5f);
    }
    __syncthreads();
    float inv = sinv;
    float4 wv = *(const float4*)(w + tid * 4);
    float4 bv = *(const float4*)(b + tid * 4);
    float y0 = v.x * inv * wv.x + bv.x;
    float y1 = v.y * inv * wv.y + bv.y;
    float y2 = v.z * inv * wv.z + bv.z;
    float y3 = v.w * inv * wv.w + bv.w;
    uint2 ph, pl;
    packhl(y0, y1, ph.x, pl.x);
    packhl(y2, y3, ph.y, pl.y);
    *(uint2*)(hi + (size_t)l * DMODEL + tid * 4) = ph;
    *(uint2*)(lo + (size_t)l * DMODEL + tid * 4) = pl;
}

// ---------------- RoPE + split (plain qkv, no partials) ----------------------------
__device__ __forceinline__ void split1(float x, __nv_bfloat16* hi, __nv_bfloat16* lo, size_t o) {
    __nv_bfloat16 h = __float2bfloat16(x);
    hi[o] = h;
    lo[o] = __float2bfloat16(x - __bfloat162float(h));
}

__global__ void rope_split_kernel(const float* __restrict__ qkv,
                                  __nv_bfloat16* __restrict__ Qh, __nv_bfloat16* __restrict__ Ql,
                                  __nv_bfloat16* __restrict__ Kh, __nv_bfloat16* __restrict__ Kl,
                                  __nv_bfloat16* __restrict__ Vh, __nv_bfloat16* __restrict__ Vl)
{
    int idx = blockIdx.x * blockDim.x + threadIdx.x;
    if (idx >= SEQ * NHEADS * (HD / 2)) return;
    int j = idx & 31;
    int h = (idx >> 5) & (NHEADS - 1);
    int l = idx >> 9;
    float inv_freq = exp2f(-(float)j * (13.287712379549449f / 32.0f));
    float ang = (float)l * inv_freq;
    float s, c;
    sincosf(ang, &s, &c);
    size_t ib = (size_t)l * QKVS + h * HD + j;
    size_t ob = (size_t)l * DMODEL + h * HD + j;
    float q1 = qkv[ib], q2 = qkv[ib + 32];
    split1((q1 * c - q2 * s) * 0.125f, Qh, Ql, ob);
    split1((q2 * c + q1 * s) * 0.125f, Qh, Ql, ob + 32);
    float k1 = qkv[ib + DMODEL], k2 = qkv[ib + DMODEL + 32];
    split1(k1 * c - k2 * s, Kh, Kl, ob);
    split1(k2 * c + k1 * s, Kh, Kl, ob + 32);
    split1(qkv[ib + 2 * DMODEL], Vh, Vl, ob);
    split1(qkv[ib + 2 * DMODEL + 32], Vh, Vl, ob + 32);
}

// ---------------- MMA flash attention, kv-split x2 (partials out) ------------------
#define ASTRIDE 144
#define AMM_SMEM (6 * 64 * ASTRIDE)

__global__ void __launch_bounds__(128) attn_mma_kernel(
    const __nv_bfloat16* __restrict__ Qh, const __nv_bfloat16* __restrict__ Ql,
    const __nv_bfloat16* __restrict__ Kh, const __nv_bfloat16* __restrict__ Kl,
    const __nv_bfloat16* __restrict__ Vh, const __nv_bfloat16* __restrict__ Vl,
    float* __restrict__ Opart, float* __restrict__ ml)
{
    extern __shared__ __align__(128) char smem[];
    const uint32_t sb = smem_u32(smem);
    const int h  = blockIdx.y;
    const int qt = blockIdx.x;
    const int z  = blockIdx.z;
    const int q0 = qt * 64;
    const int tid = threadIdx.x, wid = tid >> 5, lane = tid & 31;
    const int jmid = (qt + 2) >> 1;
    const int jlo = z ? jmid : 0;
    const int jhi = z ? (qt + 1) : jmid;

    const uint32_t QHo = 0, QLo = 9216, KHo = 18432, KLo = 27648, VHo = 36864, VLo = 46080;

    {
        const int row = tid >> 1, ho = (tid & 1) * 64;
        const uint32_t so = (uint32_t)(row * ASTRIDE + ho);
        const char* gh = (const char*)(Qh + (size_t)(q0 + row) * DMODEL + h * HD) + ho;
        const char* gl = (const char*)(Ql + (size_t)(q0 + row) * DMODEL + h * HD) + ho;
#pragma unroll
        for (int i = 0; i < 4; ++i) {
            cp16(sb + QHo + so + i * 16, gh + i * 16);
            cp16(sb + QLo + so + i * 16, gl + i * 16);
        }
    }
    CP_COMMIT();
    CP_WAIT0();
    __syncthreads();

    const int sub = lane >> 3, r8v = lane & 7;
    const uint32_t a_off = (uint32_t)(((sub & 1) * 8 + r8v) * ASTRIDE + ((sub >> 1) * 8) * 2);
    const uint32_t b_off = (uint32_t)((((sub >> 1) * 8) + r8v) * ASTRIDE + (sub & 1) * 16);
    const uint32_t v_off = (uint32_t)(((sub & 1) * 8 + r8v) * ASTRIDE + (sub >> 1) * 16);

    uint32_t qfh[4][4], qfl[4][4];
#pragma unroll
    for (int ks = 0; ks < 4; ++ks) {
        ldm4(sb + QHo + (uint32_t)(wid * 16) * ASTRIDE + a_off + (uint32_t)(ks * 32),
             qfh[ks][0], qfh[ks][1], qfh[ks][2], qfh[ks][3]);
        ldm4(sb + QLo + (uint32_t)(wid * 16) * ASTRIDE + a_off + (uint32_t)(ks * 32),
             qfl[ks][0], qfl[ks][1], qfl[ks][2], qfl[ks][3]);
    }

    float m0 = -INFINITY, m1 = -INFINITY, l0 = 0.f, l1 = 0.f;
    float oa[8][4];
#pragma unroll
    for (int nt = 0; nt < 8; ++nt)
#pragma unroll
        for (int q = 0; q < 4; ++q) oa[nt][q] = 0.f;

    const int qi0 = q0 + wid * 16 + (lane >> 2);
    const int qi1 = qi0 + 8;

    for (int jt = jlo; jt < jhi; ++jt) {
        __syncthreads();
        {
            const int row = tid >> 1, ho = (tid & 1) * 64;
            const uint32_t so = (uint32_t)(row * ASTRIDE + ho);
            const size_t g = (size_t)(jt * 64 + row) * DMODEL + h * HD;
            const char* pkh = (const char*)(Kh + g) + ho;
            const char* pkl = (const char*)(Kl + g) + ho;
            const char* pvh = (const char*)(Vh + g) + ho;
            const char* pvl = (const char*)(Vl + g) + ho;
#pragma unroll
            for (int i = 0; i < 4; ++i) {
                cp16(sb + KHo + so + i * 16, pkh + i * 16);
                cp16(sb + KLo + so + i * 16, pkl + i * 16);
                cp16(sb + VHo + so + i * 16, pvh + i * 16);
                cp16(sb + VLo + so + i * 16, pvl + i * 16);
            }
        }
        CP_COMMIT();
        CP_WAIT0();
        __syncthreads();

        float s[8][4];
#pragma unroll
        for (int nt = 0; nt < 8; ++nt)
#pragma unroll
            for (int q = 0; q < 4; ++q) s[nt][q] = 0.f;

#pragma unroll
        for (int ks = 0; ks < 4; ++ks) {
            const uint32_t ko = (uint32_t)(ks * 32);
            uint32_t kfh[8][2], kfl[8][2];
#pragma unroll
            for (int np = 0; np < 4; ++np) {
                ldm4(sb + KHo + (uint32_t)(np * 16) * ASTRIDE + b_off + ko,
                     kfh[np*2][0], kfh[np*2][1], kfh[np*2+1][0], kfh[np*2+1][1]);
                ldm4(sb + KLo + (uint32_t)(np * 16) * ASTRIDE + b_off + ko,
                     kfl[np*2][0], kfl[np*2][1], kfl[np*2+1][0], kfl[np*2+1][1]);
            }
#pragma unroll
            for (int nt = 0; nt < 8; ++nt) {
                mma16816(s[nt], qfh[ks], kfh[nt]);
                mma16816(s[nt], qfl[ks], kfh[nt]);
                mma16816(s[nt], qfh[ks], kfl[nt]);
            }
        }

        if (jt == qt) {
#pragma unroll
            for (int nt = 0; nt < 8; ++nt) {
                int kjb = jt * 64 + nt * 8 + (lane & 3) * 2;
#pragma unroll
                for (int jj = 0; jj < 2; ++jj) {
                    if (kjb + jj > qi0) s[nt][jj]     = -INFINITY;
                    if (kjb + jj > qi1) s[nt][2 + jj] = -INFINITY;
                }
            }
        }

        float rm0 = -INFINITY, rm1 = -INFINITY;
#pragma unroll
        for (int nt = 0; nt < 8; ++nt) {
            rm0 = fmaxf(rm0, fmaxf(s[nt][0], s[nt][1]));
            rm1 = fmaxf(rm1, fmaxf(s[nt][2], s[nt][3]));
        }
        rm0 = fmaxf(rm0, __shfl_xor_sync(0xffffffffu, rm0, 1));
        rm0 = fmaxf(rm0, __shfl_xor_sync(0xffffffffu, rm0, 2));
        rm1 = fmaxf(rm1, __shfl_xor_sync(0xffffffffu, rm1, 1));
        rm1 = fmaxf(rm1, __shfl_xor_sync(0xffffffffu, rm1, 2));
        float mn0 = fmaxf(m0, rm0), mn1 = fmaxf(m1, rm1);
        float al0 = __expf(m0 - mn0), al1 = __expf(m1 - mn1);
        m0 = mn0; m1 = mn1;
        float rs0 = 0.f, rs1 = 0.f;
#pragma unroll
        for (int nt = 0; nt < 8; ++nt) {
            s[nt][0] = __expf(s[nt][0] - mn0); rs0 += s[nt][0];
            s[nt][1] = __expf(s[nt][1] - mn0); rs0 += s[nt][1];
            s[nt][2] = __expf(s[nt][2] - mn1); rs1 += s[nt][2];
            s[nt][3] = __expf(s[nt][3] - mn1); rs1 += s[nt][3];
        }
        rs0 += __shfl_xor_sync(0xffffffffu, rs0, 1);
        rs0 += __shfl_xor_sync(0xffffffffu, rs0, 2);
        rs1 += __shfl_xor_sync(0xffffffffu, rs1, 1);
        rs1 += __shfl_xor_sync(0xffffffffu, rs1, 2);
        l0 = l0 * al0 + rs0;
        l1 = l1 * al1 + rs1;
#pragma unroll
        for (int nt = 0; nt < 8; ++nt) {
            oa[nt][0] *= al0; oa[nt][1] *= al0;
            oa[nt][2] *= al1; oa[nt][3] *= al1;
        }

#pragma unroll
        for (int ks = 0; ks < 4; ++ks) {
            uint32_t pah[4], pal[4];
            packhl(s[2*ks][0],   s[2*ks][1],   pah[0], pal[0]);
            packhl(s[2*ks][2],   s[2*ks][3],   pah[1], pal[1]);
            packhl(s[2*ks+1][0], s[2*ks+1][1], pah[2], pal[2]);
            packhl(s[2*ks+1][2], s[2*ks+1][3], pah[3], pal[3]);
            uint32_t vfh[8][2], vfl[8][2];
#pragma unroll
            for (int np = 0; np < 4; ++np) {
                ldm4t(sb + VHo + (uint32_t)(ks * 16) * ASTRIDE + v_off + (uint32_t)(np * 32),
                      vfh[np*2][0], vfh[np*2][1], vfh[np*2+1][0], vfh[np*2+1][1]);
                ldm4t(sb + VLo + (uint32_t)(ks * 16) * ASTRIDE + v_off + (uint32_t)(np * 32),
                      vfl[np*2][0], vfl[np*2][1], vfl[np*2+1][0], vfl[np*2+1][1]);
            }
#pragma unroll
            for (int nt = 0; nt < 8; ++nt) {
                mma16816(oa[nt], pah, vfh[nt]);
                mma16816(oa[nt], pal, vfh[nt]);
                mma16816(oa[nt], pah, vfl[nt]);
            }
        }
    }

    // ---- write unnormalized partials + (m, l) ----
    float* Op = Opart + (size_t)z * SEQ * DMODEL;
#pragma unroll
    for (int nt = 0; nt < 8; ++nt) {
        int col = h * HD + nt * 8 + (lane & 3) * 2;
        *(float2*)(Op + (size_t)qi0 * DMODEL + col) = make_float2(oa[nt][0], oa[nt][1]);
        *(float2*)(Op + (size_t)qi1 * DMODEL + col) = make_float2(oa[nt][2], oa[nt][3]);
    }
    if ((lane & 3) == 0) {
        size_t mb = (size_t)(z * NHEADS + h) * SEQ;
        *(float2*)(ml + (mb + qi0) * 2) = make_float2(m0, l0);
        *(float2*)(ml + (mb + qi1) * 2) = make_float2(m1, l1);
    }
}

// ---------------- merge attention partials -> hi/lo split --------------------------
__global__ void __launch_bounds__(256) attn_merge_kernel(
    const float* __restrict__ Opart, const float* __restrict__ ml,
    __nv_bfloat16* __restrict__ Ohi, __nv_bfloat16* __restrict__ Olo)
{
    const int l = blockIdx.x;
    const int tid = threadIdx.x;
    const int col = tid * 4;
    const int h = col >> 6;
    const size_t off = (size_t)l * DMODEL + col;
    float2 ml0 = *(const float2*)(ml + ((size_t)h * SEQ + l) * 2);
    float2 ml1 = *(const float2*)(ml + ((size_t)(NHEADS + h) * SEQ + l) * 2);
    float m = fmaxf(ml0.x, ml1.x);
    float w0 = __expf(ml0.x - m), w1 = __expf(ml1.x - m);
    float inv = 1.0f / (w0 * ml0.y + w1 * ml1.y);
    float4 a = *(const float4*)(Opart + off);
    float4 b = *(const float4*)(Opart + (size_t)SEQ * DMODEL + off);
    float o0 = (w0 * a.x + w1 * b.x) * inv;
    float o1 = (w0 * a.y + w1 * b.y) * inv;
    float o2 = (w0 * a.z + w1 * b.z) * inv;
    float o3 = (w0 * a.w + w1 * b.w) * inv;
    uint2 ph, pl;
    packhl(o0, o1, ph.x, pl.x);
    packhl(o2, o3, ph.y, pl.y);
    *(uint2*)(Ohi + off) = ph;
    *(uint2*)(Olo + off) = pl;
}

// ---------------- host launcher ----------------------------------------------------
extern "C" void kernel_launch(void* const* d_in, const int* in_sizes, int n_in,
                              void* d_out, int out_size)
{
    const float* x_in       = (const float*)d_in[0];
    const float* conv_in_w  = (const float*)d_in[1];
    const float* conv_in_b  = (const float*)d_in[2];
    const float* ln1_w      = (const float*)d_in[3];
    const float* ln1_b      = (const float*)d_in[4];
    const float* wq         = (const float*)d_in[5];
    const float* wk         = (const float*)d_in[6];
    const float* wv         = (const float*)d_in[7];
    const float* wo         = (const float*)d_in[8];
    const float* ln2_w      = (const float*)d_in[9];
    const float* ln2_b      = (const float*)d_in[10];
    const float* w1         = (const float*)d_in[11];
    const float* b1         = (const float*)d_in[12];
    const float* w2         = (const float*)d_in[13];
    const float* b2         = (const float*)d_in[14];
    const float* w3         = (const float*)d_in[15];
    const float* b3         = (const float*)d_in[16];
    const float* conv_out_w = (const float*)d_in[17];
    const float* conv_out_b = (const float*)d_in[18];
    float* out = (float*)d_out;

    float *px, *pqkv, *pml;
    __nv_bfloat16 *pAh, *pAl, *pAh2, *pAl2, *pWh, *pWl;
    __nv_bfloat16 *pQh, *pQl, *pKh, *pKl, *pVh, *pVl;
    cudaGetSymbolAddress((void**)&px,   g_x);
    cudaGetSymbolAddress((void**)&pqkv, g_qkv);
    cudaGetSymbolAddress((void**)&pml,  g_ml);
    cudaGetSymbolAddress((void**)&pAh,  g_Ah);
    cudaGetSymbolAddress((void**)&pAl,  g_Al);
    cudaGetSymbolAddress((void**)&pAh2, g_Ah2);
    cudaGetSymbolAddress((void**)&pAl2, g_Al2);
    cudaGetSymbolAddress((void**)&pWh,  g_WBh);
    cudaGetSymbolAddress((void**)&pWl,  g_WBl);
    cudaGetSymbolAddress((void**)&pQh,  g_Qh);
    cudaGetSymbolAddress((void**)&pQl,  g_Ql);
    cudaGetSymbolAddress((void**)&pKh,  g_Kh);
    cudaGetSymbolAddress((void**)&pKl,  g_Kl);
    cudaGetSymbolAddress((void**)&pVh,  g_Vh);
    cudaGetSymbolAddress((void**)&pVl,  g_Vl);

    cudaFuncSetAttribute(attn_mma_kernel, cudaFuncAttributeMaxDynamicSharedMemorySize, AMM_SMEM);
    cudaFuncSetAttribute(gemm_bf16<false, false, false, false, false>, cudaFuncAttributeMaxDynamicSharedMemorySize, GSMEM_TOTAL);
    cudaFuncSetAttribute(gemm_bf16<true,  true,  false, true,  false>, cudaFuncAttributeMaxDynamicSharedMemorySize, GSMEM_TOTAL);
    cudaFuncSetAttribute(gemm_bf16<false, false, false, false, true >, cudaFuncAttributeMaxDynamicSharedMemorySize, GSMEM_TOTAL);

    conv_in_kernel<<<(SEQ * DMODEL) / 256, 256>>>(x_in, conv_in_w, conv_in_b, px);
    splitall_kernel<<<dim3(WL_ELEMS / 16384, NLAYERS), 256>>>(wq, wk, wv, wo, w1, w2, w3, pWh, pWl);
    rmsnorm_split_kernel<<<SEQ, 256>>>(px, ln1_w, ln1_b, pAh, pAl);

    const dim3 gQKV(QKVS / 128,   SEQ / 128);
    const dim3 gDz (DMODEL / 128, SEQ / 128, 2);
    const dim3 gF  (DFF / 128,    SEQ / 128);

    for (int i = 0; i < NLAYERS; ++i) {
        const size_t wl = (size_t)i * WL_ELEMS;
        const __nv_bfloat16* qkvh = pWh + wl;
        const __nv_bfloat16* qkvl = pWl + wl;
        const __nv_bfloat16* woh  = pWh + wl + 3 * (size_t)M1;
        const __nv_bfloat16* wol  = pWl + wl + 3 * (size_t)M1;
        const __nv_bfloat16* w1h  = pWh + wl + 4 * (size_t)M1;
        const __nv_bfloat16* w1l  = pWl + wl + 4 * (size_t)M1;
        const __nv_bfloat16* w2h  = pWh + wl + 8 * (size_t)M1;
        const __nv_bfloat16* w2l  = pWl + wl + 8 * (size_t)M1;
        const __nv_bfloat16* w3h  = pWh + wl + 24 * (size_t)M1;
        const __nv_bfloat16* w3l  = pWl + wl + 24 * (size_t)M1;

        gemm_bf16<false, false, false, false, false><<<gQKV, 256, GSMEM_TOTAL>>>(
            DMODEL, DMODEL, QKVS,
            pAh, pAl, qkvh, qkvl, nullptr, nullptr, pqkv, nullptr, nullptr);

        rope_split_kernel<<<(SEQ * NHEADS * (HD / 2)) / 256, 256>>>(pqkv,
            pQh, pQl, pKh, pKl, pVh, pVl);

        // attention: kv-split x2 -> partials in pqkv (fp32) + g_ml; merge emits Ah/Al
        attn_mma_kernel<<<dim3(SEQ / 64, NHEADS, 2), 128, AMM_SMEM>>>(
            pQh, pQl, pKh, pKl, pVh, pVl, pqkv, pml);
        attn_merge_kernel<<<SEQ, 256>>>(pqkv, pml, pAh, pAl);

        // wo: K-split x2 -> fused combine + rmsnorm(ln2)
        gemm_bf16<false, false, false, false, true><<<gDz, 256, GSMEM_TOTAL>>>(
            DMODEL / 2, DMODEL, DMODEL,
            pAh, pAl, woh, wol, nullptr, nullptr, pqkv, nullptr, nullptr);
        combine_rms_kernel<false><<<SEQ, 256>>>(px, pqkv, pqkv + (size_t)SEQ * DMODEL,
            nullptr, ln2_w + i * DMODEL, ln2_b + i * DMODEL, pAh, pAl);

        gemm_bf16<true, true, false, true, false><<<gF, 256, GSMEM_TOTAL>>>(
            DMODEL, DMODEL, DFF,
            pAh, pAl, w1h, w1l, b1 + (size_t)i * DFF, nullptr, nullptr, pAh2, pAl2);

        gemm_bf16<true, true, false, true, false><<<gF, 256, GSMEM_TOTAL>>>(
            DFF, DFF, DFF,
            pAh2, pAl2, w2h, w2l, b2 + (size_t)i * DFF, nullptr, nullptr, pAh, pAl);

        // w3: K-split x2 -> fused combine(+b3) + rmsnorm(next ln1)
        gemm_bf16<false, false, false, false, true><<<gDz, 256, GSMEM_TOTAL>>>(
            DFF / 2, DFF, DMODEL,
            pAh, pAl, w3h, w3l, nullptr, nullptr, pqkv, nullptr, nullptr);
        if (i + 1 < NLAYERS) {
            combine_rms_kernel<true><<<SEQ, 256>>>(px, pqkv, pqkv + (size_t)SEQ * DMODEL,
                b3 + (size_t)i * DMODEL,
                ln1_w + (i + 1) * DMODEL, ln1_b + (i + 1) * DMODEL, pAh, pAl);
        } else {
            combine_kernel<<<(SEQ * DMODEL) / 4 / 256, 256>>>(
                px, pqkv, pqkv + (size_t)SEQ * DMODEL, b3 + (size_t)i * DMODEL);
        }
    }

    conv_out_kernel<<<dim3(SEQ, COUT), 128>>>(px, conv_out_w, conv_out_b, out);
}